// round 1
// baseline (speedup 1.0000x reference)
#include <cuda_runtime.h>

#define Bn 2
#define Sn 2048
#define Dn 1024
#define Hn 16
#define HDn 64
#define Mn (Bn*Sn)

// Scratch (allocation-free rule: device globals)
__device__ float g_q[Mn*Dn];
__device__ float g_k[Mn*Dn];
__device__ float g_v[Mn*Dn];
__device__ float g_att[Mn*Dn];
__device__ float g_cos[Sn*32];
__device__ float g_sin[Sn*32];

// ---------------------------------------------------------------------------
// RoPE tables: cos/sin(pos * 10000^(-i/32)) for pos in [0,S), i in [0,32)
// ---------------------------------------------------------------------------
__global__ void rope_table_kernel() {
    int idx = blockIdx.x * 256 + threadIdx.x;   // Sn*32 = 65536 entries
    int pos = idx >> 5;
    int i   = idx & 31;
    float inv = exp2f(-(float)i * 0.4152410118609203f);  // log2(10000)/32
    float ang = (float)pos * inv;
    float s, c;
    sincosf(ang, &s, &c);
    g_cos[idx] = c;
    g_sin[idx] = s;
}

// ---------------------------------------------------------------------------
// GEMM: C[M][N] = A[M][K] @ W[N][K]^T + bias[N], K = N = 1024, M = 4096
// 128x128 block tile, BK=16, 256 threads, 8x8 microtile as 2x2 of 4x4 halves.
// Optional fused RoPE on output (for Q and K projections).
// ---------------------------------------------------------------------------
template<bool ROPE>
__global__ void __launch_bounds__(256) gemm_kernel(
    const float* __restrict__ A, const float* __restrict__ W,
    const float* __restrict__ bias, float* __restrict__ C)
{
    const int Kd = Dn;
    __shared__ float As[16][128];
    __shared__ float Bs[16][128];

    const int t  = threadIdx.x;
    const int tx = t & 15;
    const int ty = t >> 4;
    const int m0 = blockIdx.y * 128;
    const int n0 = blockIdx.x * 128;

    float acc[2][2][4][4];
    #pragma unroll
    for (int rh = 0; rh < 2; ++rh)
        #pragma unroll
        for (int ch = 0; ch < 2; ++ch)
            #pragma unroll
            for (int i = 0; i < 4; ++i)
                #pragma unroll
                for (int j = 0; j < 4; ++j)
                    acc[rh][ch][i][j] = 0.0f;

    for (int k0 = 0; k0 < Kd; k0 += 16) {
        #pragma unroll
        for (int it = 0; it < 2; ++it) {
            int task = t + it * 256;         // 512 float4 tasks per operand
            int row  = task >> 2;            // 0..127
            int quad = task & 3;             // 0..3 (float4 within 16-wide k)
            float4 va = *(const float4*)(A + (size_t)(m0 + row) * Kd + k0 + quad * 4);
            As[quad*4+0][row] = va.x; As[quad*4+1][row] = va.y;
            As[quad*4+2][row] = va.z; As[quad*4+3][row] = va.w;
            float4 vb = *(const float4*)(W + (size_t)(n0 + row) * Kd + k0 + quad * 4);
            Bs[quad*4+0][row] = vb.x; Bs[quad*4+1][row] = vb.y;
            Bs[quad*4+2][row] = vb.z; Bs[quad*4+3][row] = vb.w;
        }
        __syncthreads();

        #pragma unroll
        for (int kk = 0; kk < 16; ++kk) {
            float a[8], b[8];
            *(float4*)&a[0] = *(const float4*)&As[kk][ty * 4];
            *(float4*)&a[4] = *(const float4*)&As[kk][64 + ty * 4];
            *(float4*)&b[0] = *(const float4*)&Bs[kk][tx * 4];
            *(float4*)&b[4] = *(const float4*)&Bs[kk][64 + tx * 4];
            #pragma unroll
            for (int rh = 0; rh < 2; ++rh)
                #pragma unroll
                for (int i = 0; i < 4; ++i)
                    #pragma unroll
                    for (int ch = 0; ch < 2; ++ch)
                        #pragma unroll
                        for (int j = 0; j < 4; ++j)
                            acc[rh][ch][i][j] += a[rh*4+i] * b[ch*4+j];
        }
        __syncthreads();
    }

    // Epilogue: bias (+ RoPE) + store
    #pragma unroll
    for (int rh = 0; rh < 2; ++rh) {
        #pragma unroll
        for (int i = 0; i < 4; ++i) {
            int row = m0 + rh * 64 + ty * 4 + i;
            int pos = row & (Sn - 1);
            #pragma unroll
            for (int ch = 0; ch < 2; ++ch) {
                int c0 = n0 + ch * 64 + tx * 4;
                float4 bz = *(const float4*)&bias[c0];
                float4 r;
                r.x = acc[rh][ch][i][0] + bz.x;
                r.y = acc[rh][ch][i][1] + bz.y;
                r.z = acc[rh][ch][i][2] + bz.z;
                r.w = acc[rh][ch][i][3] + bz.w;
                if (ROPE) {
                    int i0 = (c0 & 63) >> 1;       // even (c0 % 4 == 0)
                    float2 cc = *(const float2*)&g_cos[pos * 32 + i0];
                    float2 ss = *(const float2*)&g_sin[pos * 32 + i0];
                    float ox = r.x * cc.x - r.y * ss.x;
                    float oy = r.x * ss.x + r.y * cc.x;
                    float oz = r.z * cc.y - r.w * ss.y;
                    float ow = r.z * ss.y + r.w * cc.y;
                    r.x = ox; r.y = oy; r.z = oz; r.w = ow;
                }
                *(float4*)(C + (size_t)row * Dn + c0) = r;
            }
        }
    }
}

// ---------------------------------------------------------------------------
// Flash attention: block = (64 q-rows, head, batch). fp32, online softmax.
// Masks: causal (col <= row) AND pad (col < S - eff_len[b]).
// Shared: Qs (Q^T), KP (K^T, later aliased as P), Vs. 48 KB total.
// ---------------------------------------------------------------------------
__global__ void __launch_bounds__(256) attn_kernel(
    const float* __restrict__ Q, const float* __restrict__ K,
    const float* __restrict__ V, const int* __restrict__ eff,
    float* __restrict__ Outp)
{
    __shared__ float Qs[64][64];   // Qs[d][r]
    __shared__ float KP[64][64];   // K: KP[d][c]; later P: KP[r][c]
    __shared__ float Vs[64][64];   // Vs[c][d]

    const int q0 = blockIdx.x * 64;
    const int h  = blockIdx.y;
    const int b  = blockIdx.z;
    const int t  = threadIdx.x;
    const int tx = t & 15;
    const int ty = t >> 4;

    const int kend = Sn - eff[b];                 // keys >= kend are masked

    const float* Qb = Q + ((size_t)b * Sn + q0) * Dn + h * HDn;

    // Load Q tile transposed
    #pragma unroll
    for (int it = 0; it < 4; ++it) {
        int task = t + it * 256;      // 1024 float4 tasks
        int r  = task >> 4;
        int qd = task & 15;
        float4 vq = *(const float4*)&Qb[(size_t)r * Dn + qd * 4];
        Qs[qd*4+0][r] = vq.x; Qs[qd*4+1][r] = vq.y;
        Qs[qd*4+2][r] = vq.z; Qs[qd*4+3][r] = vq.w;
    }

    float m_i[4], l_i[4], o[4][4];
    #pragma unroll
    for (int i = 0; i < 4; ++i) {
        m_i[i] = -1e30f;
        l_i[i] = 0.0f;
        #pragma unroll
        for (int j = 0; j < 4; ++j) o[i][j] = 0.0f;
    }

    const int klimit = min(q0 + 64, kend);        // last key+1 any row needs
    const int ntiles = (klimit + 63) >> 6;

    __syncthreads();

    for (int tile = 0; tile < ntiles; ++tile) {
        const int j0 = tile * 64;
        const float* Kb = K + ((size_t)b * Sn + j0) * Dn + h * HDn;
        const float* Vb = V + ((size_t)b * Sn + j0) * Dn + h * HDn;

        #pragma unroll
        for (int it = 0; it < 4; ++it) {
            int task = t + it * 256;
            int r  = task >> 4;
            int qd = task & 15;
            float4 vk = *(const float4*)&Kb[(size_t)r * Dn + qd * 4];
            KP[qd*4+0][r] = vk.x; KP[qd*4+1][r] = vk.y;
            KP[qd*4+2][r] = vk.z; KP[qd*4+3][r] = vk.w;
            float4 vv = *(const float4*)&Vb[(size_t)r * Dn + qd * 4];
            *(float4*)&Vs[r][qd * 4] = vv;
        }
        __syncthreads();

        // S = Q K^T
        float sacc[4][4];
        #pragma unroll
        for (int i = 0; i < 4; ++i)
            #pragma unroll
            for (int j = 0; j < 4; ++j) sacc[i][j] = 0.0f;

        #pragma unroll 8
        for (int d = 0; d < 64; ++d) {
            float4 a  = *(const float4*)&Qs[d][ty * 4];
            float4 bk = *(const float4*)&KP[d][tx * 4];
            float av[4] = {a.x, a.y, a.z, a.w};
            float bv[4] = {bk.x, bk.y, bk.z, bk.w};
            #pragma unroll
            for (int i = 0; i < 4; ++i)
                #pragma unroll
                for (int j = 0; j < 4; ++j)
                    sacc[i][j] += av[i] * bv[j];
        }
        __syncthreads();   // done reading K before KP becomes P

        // scale + mask
        const bool full = (j0 + 63 <= q0) && (j0 + 64 <= kend);
        #pragma unroll
        for (int i = 0; i < 4; ++i) {
            int rowq = q0 + ty * 4 + i;
            #pragma unroll
            for (int j = 0; j < 4; ++j) {
                int col = j0 + tx * 4 + j;
                float sv = sacc[i][j] * 0.125f;
                if (!full && (col > rowq || col >= kend)) sv = -1e30f;
                sacc[i][j] = sv;
            }
        }

        // online softmax (row reductions across the 16 tx threads)
        #pragma unroll
        for (int i = 0; i < 4; ++i) {
            float mx = fmaxf(fmaxf(sacc[i][0], sacc[i][1]),
                             fmaxf(sacc[i][2], sacc[i][3]));
            #pragma unroll
            for (int off = 8; off >= 1; off >>= 1)
                mx = fmaxf(mx, __shfl_xor_sync(0xffffffffu, mx, off, 16));
            float newm = fmaxf(m_i[i], mx);
            float alpha = expf(m_i[i] - newm);
            m_i[i] = newm;
            float rs = 0.0f;
            #pragma unroll
            for (int j = 0; j < 4; ++j) {
                float p = expf(sacc[i][j] - newm);
                sacc[i][j] = p;
                rs += p;
            }
            #pragma unroll
            for (int off = 8; off >= 1; off >>= 1)
                rs += __shfl_xor_sync(0xffffffffu, rs, off, 16);
            l_i[i] = l_i[i] * alpha + rs;
            #pragma unroll
            for (int j = 0; j < 4; ++j) o[i][j] *= alpha;
        }

        // write P tile into KP
        #pragma unroll
        for (int i = 0; i < 4; ++i)
            *(float4*)&KP[ty * 4 + i][tx * 4] =
                make_float4(sacc[i][0], sacc[i][1], sacc[i][2], sacc[i][3]);
        __syncthreads();

        // O += P V
        #pragma unroll
        for (int kk0 = 0; kk0 < 64; kk0 += 4) {
            float p4[4][4];
            #pragma unroll
            for (int i = 0; i < 4; ++i) {
                float4 tmp = *(const float4*)&KP[ty * 4 + i][kk0];
                p4[i][0] = tmp.x; p4[i][1] = tmp.y;
                p4[i][2] = tmp.z; p4[i][3] = tmp.w;
            }
            #pragma unroll
            for (int jj = 0; jj < 4; ++jj) {
                float4 vv = *(const float4*)&Vs[kk0 + jj][tx * 4];
                #pragma unroll
                for (int i = 0; i < 4; ++i) {
                    float p = p4[i][jj];
                    o[i][0] += p * vv.x;
                    o[i][1] += p * vv.y;
                    o[i][2] += p * vv.z;
                    o[i][3] += p * vv.w;
                }
            }
        }
        __syncthreads();
    }

    // normalize + store
    float* Ob = Outp + ((size_t)b * Sn + q0) * Dn + h * HDn;
    #pragma unroll
    for (int i = 0; i < 4; ++i) {
        float invl = 1.0f / l_i[i];
        float4 r = make_float4(o[i][0] * invl, o[i][1] * invl,
                               o[i][2] * invl, o[i][3] * invl);
        *(float4*)&Ob[(size_t)(ty * 4 + i) * Dn + tx * 4] = r;
    }
}

// ---------------------------------------------------------------------------
extern "C" void kernel_launch(void* const* d_in, const int* in_sizes, int n_in,
                              void* d_out, int out_size)
{
    const float* x   = (const float*)d_in[0];
    const int*   eff = (const int*)d_in[1];
    const float* Wq  = (const float*)d_in[2];
    const float* bq  = (const float*)d_in[3];
    const float* Wk  = (const float*)d_in[4];
    const float* bk  = (const float*)d_in[5];
    const float* Wv  = (const float*)d_in[6];
    const float* bv  = (const float*)d_in[7];
    const float* Wo  = (const float*)d_in[8];
    const float* bo  = (const float*)d_in[9];
    float* out = (float*)d_out;

    float *q, *k, *v, *att;
    cudaGetSymbolAddress((void**)&q,   g_q);
    cudaGetSymbolAddress((void**)&k,   g_k);
    cudaGetSymbolAddress((void**)&v,   g_v);
    cudaGetSymbolAddress((void**)&att, g_att);

    rope_table_kernel<<<(Sn * 32) / 256, 256>>>();

    dim3 gg(Dn / 128, Mn / 128);   // 8 x 32
    gemm_kernel<true ><<<gg, 256>>>(x,   Wq, bq, q);
    gemm_kernel<true ><<<gg, 256>>>(x,   Wk, bk, k);
    gemm_kernel<false><<<gg, 256>>>(x,   Wv, bv, v);

    attn_kernel<<<dim3(Sn / 64, Hn, Bn), 256>>>(q, k, v, eff, att);

    gemm_kernel<false><<<gg, 256>>>(att, Wo, bo, out);
}

// round 3
// speedup vs baseline: 1.1974x; 1.1974x over previous
#include <cuda_runtime.h>
#include <cstdint>
#include <mma.h>

using namespace nvcuda;

#define Bn 2
#define Sn 2048
#define Dn 1024
#define Hn 16
#define HDn 64
#define Mn (Bn*Sn)

// Scratch (allocation-free rule: device globals)
__device__ float g_q[Mn*Dn];
__device__ float g_k[Mn*Dn];
__device__ float g_v[Mn*Dn];
__device__ float g_att[Mn*Dn];
__device__ float g_cos[Sn*32];
__device__ float g_sin[Sn*32];

// ---------------------------------------------------------------------------
__device__ __forceinline__ void cpa16(uint32_t dst, const void* src) {
    asm volatile("cp.async.cg.shared.global [%0], [%1], 16;" :: "r"(dst), "l"(src));
}
#define CP_COMMIT() asm volatile("cp.async.commit_group;" ::: "memory")
#define CP_WAIT(n)  asm volatile("cp.async.wait_group %0;" :: "n"(n) : "memory")

__device__ __forceinline__ uint32_t smem_u32(const void* p) {
    uint32_t a;
    asm("{ .reg .u64 t; cvta.to.shared.u64 t, %1; cvt.u32.u64 %0, t; }"
        : "=r"(a) : "l"(p));
    return a;
}

// ---------------------------------------------------------------------------
// RoPE tables
// ---------------------------------------------------------------------------
__global__ void rope_table_kernel() {
    int idx = blockIdx.x * 256 + threadIdx.x;   // Sn*32 entries
    int pos = idx >> 5;
    int i   = idx & 31;
    float inv = exp2f(-(float)i * 0.4152410118609203f);  // log2(10000)/32
    float ang = (float)pos * inv;
    float s, c;
    sincosf(ang, &s, &c);
    g_cos[idx] = c;
    g_sin[idx] = s;
}

// ---------------------------------------------------------------------------
// WMMA tf32 GEMM: C[M][N] = A[M][K] @ W[N][K]^T + bias, M=4096, N=K=1024
// 128x128 tile, BK=32, 8 warps (4 in M x 2 in N), warp tile 32x64.
// cp.async double buffer. Fused bias (+RoPE) epilogue through smem.
// ---------------------------------------------------------------------------
#define BK 32
#define LDT 40                         // padded row stride (floats)
#define TILE_F (128 * LDT)             // floats per operand tile
#define STAGE_F (2 * TILE_F)           // A + B
#define NCHUNK (Dn / BK)               // 32

template<bool ROPE>
__global__ void __launch_bounds__(256) gemm_wmma(
    const float* __restrict__ A, const float* __restrict__ W,
    const float* __restrict__ bias, float* __restrict__ C)
{
    extern __shared__ float smem[];    // 2 stages * STAGE_F floats (81920 B)
    const uint32_t sb = smem_u32(smem);
    const int tid = threadIdx.x;
    const int wid = tid >> 5;
    const int wm  = wid & 3;           // 0..3  (M direction, 32 rows each)
    const int wn  = wid >> 2;          // 0..1  (N direction, 64 cols each)
    const int m0 = blockIdx.y * 128, n0 = blockIdx.x * 128;

    auto loadChunk = [&](int c) {
        const int s = c & 1;
        const uint32_t abase = sb + s * STAGE_F * 4;
        const uint32_t bbase = abase + TILE_F * 4;
        const float* Ab = A + (size_t)m0 * Dn + c * BK;
        const float* Wb = W + (size_t)n0 * Dn + c * BK;
        #pragma unroll
        for (int i = 0; i < 4; ++i) {
            int task = tid + i * 256;     // 1024 tasks
            int row = task >> 3;          // 0..127
            int q   = task & 7;           // float4 within 32-float row
            uint32_t off = (uint32_t)(row * LDT + q * 4) * 4;
            cpa16(abase + off, Ab + (size_t)row * Dn + q * 4);
            cpa16(bbase + off, Wb + (size_t)row * Dn + q * 4);
        }
    };

    wmma::fragment<wmma::accumulator, 16, 16, 8, float> acc[2][4];
    #pragma unroll
    for (int i = 0; i < 2; ++i)
        #pragma unroll
        for (int j = 0; j < 4; ++j)
            wmma::fill_fragment(acc[i][j], 0.0f);

    loadChunk(0); CP_COMMIT();

    for (int c = 0; c < NCHUNK; ++c) {
        if (c + 1 < NCHUNK) { loadChunk(c + 1); CP_COMMIT(); CP_WAIT(1); }
        else                { CP_WAIT(0); }
        __syncthreads();

        const float* As = smem + (c & 1) * STAGE_F;
        const float* Bs = As + TILE_F;

        #pragma unroll
        for (int kk = 0; kk < BK; kk += 8) {
            wmma::fragment<wmma::matrix_a, 16, 16, 8, wmma::precision::tf32,
                           wmma::row_major> af[2];
            wmma::fragment<wmma::matrix_b, 16, 16, 8, wmma::precision::tf32,
                           wmma::col_major> bf[4];
            #pragma unroll
            for (int i = 0; i < 2; ++i) {
                wmma::load_matrix_sync(af[i], As + (wm * 32 + i * 16) * LDT + kk, LDT);
                #pragma unroll
                for (int e = 0; e < af[i].num_elements; ++e)
                    af[i].x[e] = wmma::__float_to_tf32(af[i].x[e]);
            }
            #pragma unroll
            for (int j = 0; j < 4; ++j) {
                wmma::load_matrix_sync(bf[j], Bs + (wn * 64 + j * 16) * LDT + kk, LDT);
                #pragma unroll
                for (int e = 0; e < bf[j].num_elements; ++e)
                    bf[j].x[e] = wmma::__float_to_tf32(bf[j].x[e]);
            }
            #pragma unroll
            for (int i = 0; i < 2; ++i)
                #pragma unroll
                for (int j = 0; j < 4; ++j)
                    wmma::mma_sync(acc[i][j], af[i], bf[j], acc[i][j]);
        }
        __syncthreads();
    }

    // Park accumulators in smem, then fused bias(+RoPE) vectorized store
    float* Cs = smem;                  // 128x128 floats = 64KB (fits in 80KB)
    #pragma unroll
    for (int i = 0; i < 2; ++i)
        #pragma unroll
        for (int j = 0; j < 4; ++j)
            wmma::store_matrix_sync(Cs + (wm * 32 + i * 16) * 128 + wn * 64 + j * 16,
                                    acc[i][j], 128, wmma::mem_row_major);
    __syncthreads();

    #pragma unroll
    for (int it = 0; it < 16; ++it) {
        int task = tid + it * 256;        // 4096 float4 tasks
        int row  = task >> 5;             // 0..127
        int c4   = task & 31;             // float4 within 128-col row
        const int c0 = n0 + c4 * 4;
        float4 r = *(const float4*)&Cs[row * 128 + c4 * 4];
        float4 bz = *(const float4*)&bias[c0];
        r.x += bz.x; r.y += bz.y; r.z += bz.z; r.w += bz.w;
        if (ROPE) {
            int pos = (m0 + row) & (Sn - 1);
            int i0 = (c0 & 63) >> 1;
            float2 cc = *(const float2*)&g_cos[pos * 32 + i0];
            float2 ss = *(const float2*)&g_sin[pos * 32 + i0];
            float ox = r.x * cc.x - r.y * ss.x;
            float oy = r.x * ss.x + r.y * cc.x;
            float oz = r.z * cc.y - r.w * ss.y;
            float ow = r.z * ss.y + r.w * cc.y;
            r.x = ox; r.y = oy; r.z = oz; r.w = ow;
        }
        *(float4*)(C + (size_t)(m0 + row) * Dn + c0) = r;
    }
}

// ---------------------------------------------------------------------------
// Flash attention (fp32): block = (64 q-rows, head, batch)
// ---------------------------------------------------------------------------
__global__ void __launch_bounds__(256) attn_kernel(
    const float* __restrict__ Q, const float* __restrict__ K,
    const float* __restrict__ V, const int* __restrict__ eff,
    float* __restrict__ Outp)
{
    __shared__ float Qs[64][64];
    __shared__ float KP[64][64];
    __shared__ float Vs[64][64];

    const int q0 = blockIdx.x * 64;
    const int h  = blockIdx.y;
    const int b  = blockIdx.z;
    const int t  = threadIdx.x;
    const int tx = t & 15;
    const int ty = t >> 4;

    const int kend = Sn - eff[b];

    const float* Qb = Q + ((size_t)b * Sn + q0) * Dn + h * HDn;

    #pragma unroll
    for (int it = 0; it < 4; ++it) {
        int task = t + it * 256;
        int r  = task >> 4;
        int qd = task & 15;
        float4 vq = *(const float4*)&Qb[(size_t)r * Dn + qd * 4];
        Qs[qd*4+0][r] = vq.x; Qs[qd*4+1][r] = vq.y;
        Qs[qd*4+2][r] = vq.z; Qs[qd*4+3][r] = vq.w;
    }

    float m_i[4], l_i[4], o[4][4];
    #pragma unroll
    for (int i = 0; i < 4; ++i) {
        m_i[i] = -1e30f;
        l_i[i] = 0.0f;
        #pragma unroll
        for (int j = 0; j < 4; ++j) o[i][j] = 0.0f;
    }

    const int klimit = min(q0 + 64, kend);
    const int ntiles = (klimit + 63) >> 6;

    __syncthreads();

    for (int tile = 0; tile < ntiles; ++tile) {
        const int j0 = tile * 64;
        const float* Kb = K + ((size_t)b * Sn + j0) * Dn + h * HDn;
        const float* Vb = V + ((size_t)b * Sn + j0) * Dn + h * HDn;

        #pragma unroll
        for (int it = 0; it < 4; ++it) {
            int task = t + it * 256;
            int r  = task >> 4;
            int qd = task & 15;
            float4 vk = *(const float4*)&Kb[(size_t)r * Dn + qd * 4];
            KP[qd*4+0][r] = vk.x; KP[qd*4+1][r] = vk.y;
            KP[qd*4+2][r] = vk.z; KP[qd*4+3][r] = vk.w;
            float4 vv = *(const float4*)&Vb[(size_t)r * Dn + qd * 4];
            *(float4*)&Vs[r][qd * 4] = vv;
        }
        __syncthreads();

        float sacc[4][4];
        #pragma unroll
        for (int i = 0; i < 4; ++i)
            #pragma unroll
            for (int j = 0; j < 4; ++j) sacc[i][j] = 0.0f;

        #pragma unroll 8
        for (int d = 0; d < 64; ++d) {
            float4 a  = *(const float4*)&Qs[d][ty * 4];
            float4 bk = *(const float4*)&KP[d][tx * 4];
            float av[4] = {a.x, a.y, a.z, a.w};
            float bv[4] = {bk.x, bk.y, bk.z, bk.w};
            #pragma unroll
            for (int i = 0; i < 4; ++i)
                #pragma unroll
                for (int j = 0; j < 4; ++j)
                    sacc[i][j] += av[i] * bv[j];
        }
        __syncthreads();

        const bool full = (j0 + 63 <= q0) && (j0 + 64 <= kend);
        #pragma unroll
        for (int i = 0; i < 4; ++i) {
            int rowq = q0 + ty * 4 + i;
            #pragma unroll
            for (int j = 0; j < 4; ++j) {
                int col = j0 + tx * 4 + j;
                float sv = sacc[i][j] * 0.125f;
                if (!full && (col > rowq || col >= kend)) sv = -1e30f;
                sacc[i][j] = sv;
            }
        }

        #pragma unroll
        for (int i = 0; i < 4; ++i) {
            float mx = fmaxf(fmaxf(sacc[i][0], sacc[i][1]),
                             fmaxf(sacc[i][2], sacc[i][3]));
            #pragma unroll
            for (int off = 8; off >= 1; off >>= 1)
                mx = fmaxf(mx, __shfl_xor_sync(0xffffffffu, mx, off, 16));
            float newm = fmaxf(m_i[i], mx);
            float alpha = expf(m_i[i] - newm);
            m_i[i] = newm;
            float rs = 0.0f;
            #pragma unroll
            for (int j = 0; j < 4; ++j) {
                float p = expf(sacc[i][j] - newm);
                sacc[i][j] = p;
                rs += p;
            }
            #pragma unroll
            for (int off = 8; off >= 1; off >>= 1)
                rs += __shfl_xor_sync(0xffffffffu, rs, off, 16);
            l_i[i] = l_i[i] * alpha + rs;
            #pragma unroll
            for (int j = 0; j < 4; ++j) o[i][j] *= alpha;
        }

        #pragma unroll
        for (int i = 0; i < 4; ++i)
            *(float4*)&KP[ty * 4 + i][tx * 4] =
                make_float4(sacc[i][0], sacc[i][1], sacc[i][2], sacc[i][3]);
        __syncthreads();

        #pragma unroll
        for (int kk0 = 0; kk0 < 64; kk0 += 4) {
            float p4[4][4];
            #pragma unroll
            for (int i = 0; i < 4; ++i) {
                float4 tmp = *(const float4*)&KP[ty * 4 + i][kk0];
                p4[i][0] = tmp.x; p4[i][1] = tmp.y;
                p4[i][2] = tmp.z; p4[i][3] = tmp.w;
            }
            #pragma unroll
            for (int jj = 0; jj < 4; ++jj) {
                float4 vv = *(const float4*)&Vs[kk0 + jj][tx * 4];
                #pragma unroll
                for (int i = 0; i < 4; ++i) {
                    float p = p4[i][jj];
                    o[i][0] += p * vv.x;
                    o[i][1] += p * vv.y;
                    o[i][2] += p * vv.z;
                    o[i][3] += p * vv.w;
                }
            }
        }
        __syncthreads();
    }

    float* Ob = Outp + ((size_t)b * Sn + q0) * Dn + h * HDn;
    #pragma unroll
    for (int i = 0; i < 4; ++i) {
        float invl = 1.0f / l_i[i];
        float4 r = make_float4(o[i][0] * invl, o[i][1] * invl,
                               o[i][2] * invl, o[i][3] * invl);
        *(float4*)&Ob[(size_t)(ty * 4 + i) * Dn + tx * 4] = r;
    }
}

// ---------------------------------------------------------------------------
extern "C" void kernel_launch(void* const* d_in, const int* in_sizes, int n_in,
                              void* d_out, int out_size)
{
    const float* x   = (const float*)d_in[0];
    const int*   eff = (const int*)d_in[1];
    const float* Wq  = (const float*)d_in[2];
    const float* bq  = (const float*)d_in[3];
    const float* Wk  = (const float*)d_in[4];
    const float* bk  = (const float*)d_in[5];
    const float* Wv  = (const float*)d_in[6];
    const float* bv  = (const float*)d_in[7];
    const float* Wo  = (const float*)d_in[8];
    const float* bo  = (const float*)d_in[9];
    float* out = (float*)d_out;

    float *q, *k, *v, *att;
    cudaGetSymbolAddress((void**)&q,   g_q);
    cudaGetSymbolAddress((void**)&k,   g_k);
    cudaGetSymbolAddress((void**)&v,   g_v);
    cudaGetSymbolAddress((void**)&att, g_att);

    const int smem_bytes = 2 * STAGE_F * 4;   // 81920 B
    cudaFuncSetAttribute(gemm_wmma<true>,
                         cudaFuncAttributeMaxDynamicSharedMemorySize, smem_bytes);
    cudaFuncSetAttribute(gemm_wmma<false>,
                         cudaFuncAttributeMaxDynamicSharedMemorySize, smem_bytes);

    rope_table_kernel<<<(Sn * 32) / 256, 256>>>();

    dim3 gg(Dn / 128, Mn / 128);   // 8 x 32
    gemm_wmma<true ><<<gg, 256, smem_bytes>>>(x,   Wq, bq, q);
    gemm_wmma<true ><<<gg, 256, smem_bytes>>>(x,   Wk, bk, k);
    gemm_wmma<false><<<gg, 256, smem_bytes>>>(x,   Wv, bv, v);

    attn_kernel<<<dim3(Sn / 64, Hn, Bn), 256>>>(q, k, v, eff, att);

    gemm_wmma<false><<<gg, 256, smem_bytes>>>(att, Wo, bo, out);
}

// round 4
// speedup vs baseline: 1.5329x; 1.2802x over previous
#include <cuda_runtime.h>
#include <cuda_bf16.h>
#include <cstdint>
#include <mma.h>

using namespace nvcuda;

#define Bn 2
#define Sn 2048
#define Dn 1024
#define Hn 16
#define HDn 64
#define Mn (Bn*Sn)

// Scratch (allocation-free rule: device globals)
__device__ float g_q[Mn*Dn];
__device__ float g_k[Mn*Dn];
__device__ float g_v[Mn*Dn];
__device__ float g_att[Mn*Dn];
__device__ float g_cos[Sn*32];
__device__ float g_sin[Sn*32];
__device__ __nv_bfloat16 g_qh[Mn*Dn], g_ql[Mn*Dn];
__device__ __nv_bfloat16 g_kh[Mn*Dn], g_kl[Mn*Dn];
__device__ __nv_bfloat16 g_vh[Mn*Dn], g_vl[Mn*Dn];

// ---------------------------------------------------------------------------
__device__ __forceinline__ void cpa16(uint32_t dst, const void* src) {
    asm volatile("cp.async.cg.shared.global [%0], [%1], 16;" :: "r"(dst), "l"(src));
}
#define CP_COMMIT() asm volatile("cp.async.commit_group;" ::: "memory")
#define CP_WAIT(n)  asm volatile("cp.async.wait_group %0;" :: "n"(n) : "memory")

__device__ __forceinline__ uint32_t smem_u32(const void* p) {
    uint32_t a;
    asm("{ .reg .u64 t; cvta.to.shared.u64 t, %1; cvt.u32.u64 %0, t; }"
        : "=r"(a) : "l"(p));
    return a;
}

// mma.sync m16n8k16 bf16 -> f32
#define MMA16816(c, a0, a1, a2, a3, b0, b1)                                   \
    asm volatile(                                                             \
        "mma.sync.aligned.m16n8k16.row.col.f32.bf16.bf16.f32 "                \
        "{%0,%1,%2,%3}, {%4,%5,%6,%7}, {%8,%9}, {%0,%1,%2,%3};"               \
        : "+f"((c)[0]), "+f"((c)[1]), "+f"((c)[2]), "+f"((c)[3])              \
        : "r"(a0), "r"(a1), "r"(a2), "r"(a3), "r"(b0), "r"(b1))

// ---------------------------------------------------------------------------
// RoPE tables
// ---------------------------------------------------------------------------
__global__ void rope_table_kernel() {
    int idx = blockIdx.x * 256 + threadIdx.x;   // Sn*32 entries
    int pos = idx >> 5;
    int i   = idx & 31;
    float inv = exp2f(-(float)i * 0.4152410118609203f);  // log2(10000)/32
    float ang = (float)pos * inv;
    float s, c;
    sincosf(ang, &s, &c);
    g_cos[idx] = c;
    g_sin[idx] = s;
}

// ---------------------------------------------------------------------------
// WMMA tf32 GEMM (unchanged from R3): C = A @ W^T + bias (+RoPE)
// ---------------------------------------------------------------------------
#define BK 32
#define LDT 40
#define TILE_F (128 * LDT)
#define STAGE_F (2 * TILE_F)
#define NCHUNK (Dn / BK)

template<bool ROPE>
__global__ void __launch_bounds__(256) gemm_wmma(
    const float* __restrict__ A, const float* __restrict__ W,
    const float* __restrict__ bias, float* __restrict__ C)
{
    extern __shared__ float smem[];
    const uint32_t sb = smem_u32(smem);
    const int tid = threadIdx.x;
    const int wid = tid >> 5;
    const int wm  = wid & 3;
    const int wn  = wid >> 2;
    const int m0 = blockIdx.y * 128, n0 = blockIdx.x * 128;

    auto loadChunk = [&](int c) {
        const int s = c & 1;
        const uint32_t abase = sb + s * STAGE_F * 4;
        const uint32_t bbase = abase + TILE_F * 4;
        const float* Ab = A + (size_t)m0 * Dn + c * BK;
        const float* Wb = W + (size_t)n0 * Dn + c * BK;
        #pragma unroll
        for (int i = 0; i < 4; ++i) {
            int task = tid + i * 256;
            int row = task >> 3;
            int q   = task & 7;
            uint32_t off = (uint32_t)(row * LDT + q * 4) * 4;
            cpa16(abase + off, Ab + (size_t)row * Dn + q * 4);
            cpa16(bbase + off, Wb + (size_t)row * Dn + q * 4);
        }
    };

    wmma::fragment<wmma::accumulator, 16, 16, 8, float> acc[2][4];
    #pragma unroll
    for (int i = 0; i < 2; ++i)
        #pragma unroll
        for (int j = 0; j < 4; ++j)
            wmma::fill_fragment(acc[i][j], 0.0f);

    loadChunk(0); CP_COMMIT();

    for (int c = 0; c < NCHUNK; ++c) {
        if (c + 1 < NCHUNK) { loadChunk(c + 1); CP_COMMIT(); CP_WAIT(1); }
        else                { CP_WAIT(0); }
        __syncthreads();

        const float* As = smem + (c & 1) * STAGE_F;
        const float* Bs = As + TILE_F;

        #pragma unroll
        for (int kk = 0; kk < BK; kk += 8) {
            wmma::fragment<wmma::matrix_a, 16, 16, 8, wmma::precision::tf32,
                           wmma::row_major> af[2];
            wmma::fragment<wmma::matrix_b, 16, 16, 8, wmma::precision::tf32,
                           wmma::col_major> bf[4];
            #pragma unroll
            for (int i = 0; i < 2; ++i) {
                wmma::load_matrix_sync(af[i], As + (wm * 32 + i * 16) * LDT + kk, LDT);
                #pragma unroll
                for (int e = 0; e < af[i].num_elements; ++e)
                    af[i].x[e] = wmma::__float_to_tf32(af[i].x[e]);
            }
            #pragma unroll
            for (int j = 0; j < 4; ++j) {
                wmma::load_matrix_sync(bf[j], Bs + (wn * 64 + j * 16) * LDT + kk, LDT);
                #pragma unroll
                for (int e = 0; e < bf[j].num_elements; ++e)
                    bf[j].x[e] = wmma::__float_to_tf32(bf[j].x[e]);
            }
            #pragma unroll
            for (int i = 0; i < 2; ++i)
                #pragma unroll
                for (int j = 0; j < 4; ++j)
                    wmma::mma_sync(acc[i][j], af[i], bf[j], acc[i][j]);
        }
        __syncthreads();
    }

    float* Cs = smem;
    #pragma unroll
    for (int i = 0; i < 2; ++i)
        #pragma unroll
        for (int j = 0; j < 4; ++j)
            wmma::store_matrix_sync(Cs + (wm * 32 + i * 16) * 128 + wn * 64 + j * 16,
                                    acc[i][j], 128, wmma::mem_row_major);
    __syncthreads();

    #pragma unroll
    for (int it = 0; it < 16; ++it) {
        int task = tid + it * 256;
        int row  = task >> 5;
        int c4   = task & 31;
        const int c0 = n0 + c4 * 4;
        float4 r = *(const float4*)&Cs[row * 128 + c4 * 4];
        float4 bz = *(const float4*)&bias[c0];
        r.x += bz.x; r.y += bz.y; r.z += bz.z; r.w += bz.w;
        if (ROPE) {
            int pos = (m0 + row) & (Sn - 1);
            int i0 = (c0 & 63) >> 1;
            float2 cc = *(const float2*)&g_cos[pos * 32 + i0];
            float2 ss = *(const float2*)&g_sin[pos * 32 + i0];
            float ox = r.x * cc.x - r.y * ss.x;
            float oy = r.x * ss.x + r.y * cc.x;
            float oz = r.z * cc.y - r.w * ss.y;
            float ow = r.z * ss.y + r.w * cc.y;
            r.x = ox; r.y = oy; r.z = oz; r.w = ow;
        }
        *(float4*)(C + (size_t)(m0 + row) * Dn + c0) = r;
    }
}

// ---------------------------------------------------------------------------
// hi/lo bf16 split of q (x0.125), k, v
// ---------------------------------------------------------------------------
__global__ void conv_kernel() {
    int idx = blockIdx.x * 256 + threadIdx.x;   // Mn*Dn/2 threads
    int i = idx * 2;

    float2 q = *(const float2*)&g_q[i];
    q.x *= 0.125f; q.y *= 0.125f;
    __nv_bfloat16 qx = __float2bfloat16(q.x), qy = __float2bfloat16(q.y);
    __nv_bfloat162 qh2; qh2.x = qx; qh2.y = qy;
    *(__nv_bfloat162*)&g_qh[i] = qh2;
    __nv_bfloat162 ql2;
    ql2.x = __float2bfloat16(q.x - __bfloat162float(qx));
    ql2.y = __float2bfloat16(q.y - __bfloat162float(qy));
    *(__nv_bfloat162*)&g_ql[i] = ql2;

    float2 k = *(const float2*)&g_k[i];
    __nv_bfloat16 kx = __float2bfloat16(k.x), ky = __float2bfloat16(k.y);
    __nv_bfloat162 kh2; kh2.x = kx; kh2.y = ky;
    *(__nv_bfloat162*)&g_kh[i] = kh2;
    __nv_bfloat162 kl2;
    kl2.x = __float2bfloat16(k.x - __bfloat162float(kx));
    kl2.y = __float2bfloat16(k.y - __bfloat162float(ky));
    *(__nv_bfloat162*)&g_kl[i] = kl2;

    float2 v = *(const float2*)&g_v[i];
    __nv_bfloat16 vx = __float2bfloat16(v.x), vy = __float2bfloat16(v.y);
    __nv_bfloat162 vh2; vh2.x = vx; vh2.y = vy;
    *(__nv_bfloat162*)&g_vh[i] = vh2;
    __nv_bfloat162 vl2;
    vl2.x = __float2bfloat16(v.x - __bfloat162float(vx));
    vl2.y = __float2bfloat16(v.y - __bfloat162float(vy));
    *(__nv_bfloat162*)&g_vl[i] = vl2;
}

// ---------------------------------------------------------------------------
// Flash attention v2: tensor-core bf16x3, 128 q-rows per CTA, k-tile 64.
// 8 warps x 16 q-rows. Online softmax on fp32 S tile in smem.
// smem layout (bytes):
//   Ss  [128][66] f32    @ 0       (33792)
//   Ph  [128][72] bf16   @ 33792   (18432)
//   Pl  [128][72] bf16   @ 52224   (18432)
//   Kh  [64][72]  bf16   @ 70656   (9216)
//   Kl  [64][72]  bf16   @ 79872   (9216)
//   Vh  [64d][72k] bf16  @ 89088   (9216)   (transposed)
//   Vl  [64d][72k] bf16  @ 98304   (9216)
//   Sm/Sl/Sa [128] f32   @ 107520/108032/108544
// total 109056
// ---------------------------------------------------------------------------
#define SLDS 66
#define SLD  72
#define ATT_SMEM 109056

__global__ void __launch_bounds__(256) attn2(const int* __restrict__ eff,
                                             float* __restrict__ Outp)
{
    extern __shared__ char sm[];
    float*         Ss = (float*)sm;
    __nv_bfloat16* Ph = (__nv_bfloat16*)(sm + 33792);
    __nv_bfloat16* Pl = (__nv_bfloat16*)(sm + 52224);
    __nv_bfloat16* Kh = (__nv_bfloat16*)(sm + 70656);
    __nv_bfloat16* Kl = (__nv_bfloat16*)(sm + 79872);
    __nv_bfloat16* Vh = (__nv_bfloat16*)(sm + 89088);
    __nv_bfloat16* Vl = (__nv_bfloat16*)(sm + 98304);
    float*         Sm = (float*)(sm + 107520);
    float*         Sl = (float*)(sm + 108032);
    float*         Sa = (float*)(sm + 108544);

    const int t = threadIdx.x, w = t >> 5, lane = t & 31;
    const int g = lane >> 2, tig = lane & 3;
    const int q0 = ((int)gridDim.x - 1 - (int)blockIdx.x) * 128;  // big q first
    const int h = blockIdx.y, b = blockIdx.z;
    const int kend = Sn - eff[b];

    const size_t bofs = (size_t)b * Sn * Dn + h * HDn;

    // --- cache Q fragments (hi/lo) in registers: rows w*16+g, +8 ---
    uint32_t qhf[4][4], qlf[4][4];
    {
        const __nv_bfloat16* bh = g_qh + bofs + (size_t)(q0 + w * 16 + g) * Dn;
        const __nv_bfloat16* bl = g_ql + bofs + (size_t)(q0 + w * 16 + g) * Dn;
        #pragma unroll
        for (int ks = 0; ks < 4; ++ks) {
            int d0 = ks * 16 + 2 * tig;
            qhf[ks][0] = *(const uint32_t*)(bh + d0);
            qhf[ks][1] = *(const uint32_t*)(bh + 8 * (size_t)Dn + d0);
            qhf[ks][2] = *(const uint32_t*)(bh + d0 + 8);
            qhf[ks][3] = *(const uint32_t*)(bh + 8 * (size_t)Dn + d0 + 8);
            qlf[ks][0] = *(const uint32_t*)(bl + d0);
            qlf[ks][1] = *(const uint32_t*)(bl + 8 * (size_t)Dn + d0);
            qlf[ks][2] = *(const uint32_t*)(bl + d0 + 8);
            qlf[ks][3] = *(const uint32_t*)(bl + 8 * (size_t)Dn + d0 + 8);
        }
    }

    float oc[8][4];
    #pragma unroll
    for (int n = 0; n < 8; ++n) { oc[n][0]=0.f; oc[n][1]=0.f; oc[n][2]=0.f; oc[n][3]=0.f; }

    if (t < 128) { Sm[t] = -1e30f; Sl[t] = 0.f; }
    __syncthreads();

    const int klimit = min(q0 + 128, kend);
    const int nt = (klimit + 63) >> 6;

    for (int tile = 0; tile < nt; ++tile) {
        const int j0 = tile * 64;
        const __nv_bfloat16* KgH = g_kh + bofs + (size_t)j0 * Dn;
        const __nv_bfloat16* KgL = g_kl + bofs + (size_t)j0 * Dn;
        const __nv_bfloat16* VgH = g_vh + bofs + (size_t)j0 * Dn;
        const __nv_bfloat16* VgL = g_vl + bofs + (size_t)j0 * Dn;

        // load K (row-major [k][d]) and V (transposed [d][k]) hi/lo tiles
        #pragma unroll
        for (int i2 = 0; i2 < 8; ++i2) {
            int task = t + i2 * 256;
            int kr = task >> 5;
            int d0 = (task & 31) * 2;
            *(uint32_t*)&Kh[kr * SLD + d0] = *(const uint32_t*)(KgH + (size_t)kr * Dn + d0);
            *(uint32_t*)&Kl[kr * SLD + d0] = *(const uint32_t*)(KgL + (size_t)kr * Dn + d0);
            __nv_bfloat162 vh2 = *(const __nv_bfloat162*)(VgH + (size_t)kr * Dn + d0);
            Vh[d0 * SLD + kr]       = vh2.x;
            Vh[(d0 + 1) * SLD + kr] = vh2.y;
            __nv_bfloat162 vl2 = *(const __nv_bfloat162*)(VgL + (size_t)kr * Dn + d0);
            Vl[d0 * SLD + kr]       = vl2.x;
            Vl[(d0 + 1) * SLD + kr] = vl2.y;
        }
        __syncthreads();

        // --- S = Q K^T (bf16x3) ---
        #pragma unroll
        for (int n = 0; n < 8; ++n) {
            float c[4] = {0.f, 0.f, 0.f, 0.f};
            const int krow = (n * 8 + g) * SLD;
            #pragma unroll
            for (int ks = 0; ks < 4; ++ks) {
                int dd = ks * 16 + 2 * tig;
                uint32_t b0h = *(uint32_t*)&Kh[krow + dd];
                uint32_t b1h = *(uint32_t*)&Kh[krow + dd + 8];
                uint32_t b0l = *(uint32_t*)&Kl[krow + dd];
                uint32_t b1l = *(uint32_t*)&Kl[krow + dd + 8];
                MMA16816(c, qhf[ks][0], qhf[ks][1], qhf[ks][2], qhf[ks][3], b0h, b1h);
                MMA16816(c, qhf[ks][0], qhf[ks][1], qhf[ks][2], qhf[ks][3], b0l, b1l);
                MMA16816(c, qlf[ks][0], qlf[ks][1], qlf[ks][2], qlf[ks][3], b0h, b1h);
            }
            int rr = w * 16 + g, cc = n * 8 + 2 * tig;
            *(float2*)&Ss[rr * SLDS + cc]       = make_float2(c[0], c[1]);
            *(float2*)&Ss[(rr + 8) * SLDS + cc] = make_float2(c[2], c[3]);
        }
        __syncthreads();

        // --- masked online softmax; write P hi/lo ---
        {
            const int r = t >> 1, half = t & 1;
            const int rowg = q0 + r;
            const int cbase = half * 32;
            float pv[32];
            float mx = -1e30f;
            #pragma unroll
            for (int j = 0; j < 32; ++j) {
                int cg = j0 + cbase + j;
                float s = Ss[r * SLDS + cbase + j];
                bool ok = (cg <= rowg) && (cg < kend);
                float sv = ok ? s : -1e30f;
                pv[j] = sv;
                mx = fmaxf(mx, sv);
            }
            mx = fmaxf(mx, __shfl_xor_sync(0xffffffffu, mx, 1));
            float mold = Sm[r];
            float nm = fmaxf(mold, mx);
            float al = __expf(mold - nm);
            float sum = 0.f;
            #pragma unroll
            for (int j = 0; j < 32; ++j) {
                float p = __expf(pv[j] - nm);
                pv[j] = p;
                sum += p;
            }
            sum += __shfl_xor_sync(0xffffffffu, sum, 1);
            if (half == 0) {
                Sm[r] = nm;
                Sl[r] = Sl[r] * al + sum;
                Sa[r] = al;
            }
            #pragma unroll
            for (int j = 0; j < 32; j += 2) {
                __nv_bfloat16 h0 = __float2bfloat16(pv[j]);
                __nv_bfloat16 h1 = __float2bfloat16(pv[j + 1]);
                __nv_bfloat162 hh; hh.x = h0; hh.y = h1;
                *(__nv_bfloat162*)&Ph[r * SLD + cbase + j] = hh;
                __nv_bfloat162 ll;
                ll.x = __float2bfloat16(pv[j]     - __bfloat162float(h0));
                ll.y = __float2bfloat16(pv[j + 1] - __bfloat162float(h1));
                *(__nv_bfloat162*)&Pl[r * SLD + cbase + j] = ll;
            }
        }
        __syncthreads();

        // --- rescale O, then O += P V (bf16x3) ---
        {
            float aA = Sa[w * 16 + g];
            float aB = Sa[w * 16 + g + 8];
            #pragma unroll
            for (int n = 0; n < 8; ++n) {
                oc[n][0] *= aA; oc[n][1] *= aA;
                oc[n][2] *= aB; oc[n][3] *= aB;
            }
            const int pr = (w * 16 + g) * SLD;
            #pragma unroll
            for (int ks = 0; ks < 4; ++ks) {
                int kk = ks * 16 + 2 * tig;
                uint32_t ah0 = *(uint32_t*)&Ph[pr + kk];
                uint32_t ah1 = *(uint32_t*)&Ph[pr + 8 * SLD + kk];
                uint32_t ah2 = *(uint32_t*)&Ph[pr + kk + 8];
                uint32_t ah3 = *(uint32_t*)&Ph[pr + 8 * SLD + kk + 8];
                uint32_t al0 = *(uint32_t*)&Pl[pr + kk];
                uint32_t al1 = *(uint32_t*)&Pl[pr + 8 * SLD + kk];
                uint32_t al2 = *(uint32_t*)&Pl[pr + kk + 8];
                uint32_t al3 = *(uint32_t*)&Pl[pr + 8 * SLD + kk + 8];
                #pragma unroll
                for (int n = 0; n < 8; ++n) {
                    const int vrow = (n * 8 + g) * SLD;
                    uint32_t b0h = *(uint32_t*)&Vh[vrow + kk];
                    uint32_t b1h = *(uint32_t*)&Vh[vrow + kk + 8];
                    uint32_t b0l = *(uint32_t*)&Vl[vrow + kk];
                    uint32_t b1l = *(uint32_t*)&Vl[vrow + kk + 8];
                    MMA16816(oc[n], ah0, ah1, ah2, ah3, b0h, b1h);
                    MMA16816(oc[n], ah0, ah1, ah2, ah3, b0l, b1l);
                    MMA16816(oc[n], al0, al1, al2, al3, b0h, b1h);
                }
            }
        }
        __syncthreads();
    }

    // --- epilogue: normalize + store ---
    float invA = 1.f / Sl[w * 16 + g];
    float invB = 1.f / Sl[w * 16 + g + 8];
    float* Ob = Outp + bofs + (size_t)(q0 + w * 16 + g) * Dn;
    #pragma unroll
    for (int n = 0; n < 8; ++n) {
        int cc = n * 8 + 2 * tig;
        *(float2*)&Ob[cc] = make_float2(oc[n][0] * invA, oc[n][1] * invA);
        *(float2*)(Ob + 8 * (size_t)Dn + cc) =
            make_float2(oc[n][2] * invB, oc[n][3] * invB);
    }
}

// ---------------------------------------------------------------------------
extern "C" void kernel_launch(void* const* d_in, const int* in_sizes, int n_in,
                              void* d_out, int out_size)
{
    const float* x   = (const float*)d_in[0];
    const int*   eff = (const int*)d_in[1];
    const float* Wq  = (const float*)d_in[2];
    const float* bq  = (const float*)d_in[3];
    const float* Wk  = (const float*)d_in[4];
    const float* bk  = (const float*)d_in[5];
    const float* Wv  = (const float*)d_in[6];
    const float* bv  = (const float*)d_in[7];
    const float* Wo  = (const float*)d_in[8];
    const float* bo  = (const float*)d_in[9];
    float* out = (float*)d_out;

    float *q, *k, *v, *att;
    cudaGetSymbolAddress((void**)&q,   g_q);
    cudaGetSymbolAddress((void**)&k,   g_k);
    cudaGetSymbolAddress((void**)&v,   g_v);
    cudaGetSymbolAddress((void**)&att, g_att);

    const int smem_bytes = 2 * STAGE_F * 4;   // 81920 B
    cudaFuncSetAttribute(gemm_wmma<true>,
                         cudaFuncAttributeMaxDynamicSharedMemorySize, smem_bytes);
    cudaFuncSetAttribute(gemm_wmma<false>,
                         cudaFuncAttributeMaxDynamicSharedMemorySize, smem_bytes);
    cudaFuncSetAttribute(attn2,
                         cudaFuncAttributeMaxDynamicSharedMemorySize, ATT_SMEM);

    rope_table_kernel<<<(Sn * 32) / 256, 256>>>();

    dim3 gg(Dn / 128, Mn / 128);   // 8 x 32
    gemm_wmma<true ><<<gg, 256, smem_bytes>>>(x,   Wq, bq, q);
    gemm_wmma<true ><<<gg, 256, smem_bytes>>>(x,   Wk, bk, k);
    gemm_wmma<false><<<gg, 256, smem_bytes>>>(x,   Wv, bv, v);

    conv_kernel<<<(Mn * Dn / 2) / 256, 256>>>();

    attn2<<<dim3(Sn / 128, Hn, Bn), 256, ATT_SMEM>>>(eff, att);

    gemm_wmma<false><<<gg, 256, smem_bytes>>>(att, Wo, bo, out);
}

// round 5
// speedup vs baseline: 2.4524x; 1.5998x over previous
#include <cuda_runtime.h>
#include <cuda_bf16.h>
#include <cstdint>

#define Bn 2
#define Sn 2048
#define Dn 1024
#define Hn 16
#define HDn 64
#define Mn (Bn*Sn)

// Scratch (allocation-free rule: device globals)
__device__ float g_att[Mn*Dn];
__device__ float g_xr[Mn*Dn];                 // tf32-rounded x
__device__ float g_wqr[Dn*Dn], g_wkr[Dn*Dn], g_wvr[Dn*Dn], g_wor[Dn*Dn];
__device__ float g_cos[Sn*32];
__device__ float g_sin[Sn*32];
__device__ __nv_bfloat16 g_qh[Mn*Dn], g_ql[Mn*Dn];
__device__ __nv_bfloat16 g_kh[Mn*Dn], g_kl[Mn*Dn];
__device__ __nv_bfloat16 g_vh[Mn*Dn], g_vl[Mn*Dn];

// ---------------------------------------------------------------------------
__device__ __forceinline__ void cpa16(uint32_t dst, const void* src) {
    asm volatile("cp.async.cg.shared.global [%0], [%1], 16;" :: "r"(dst), "l"(src));
}
#define CP_COMMIT() asm volatile("cp.async.commit_group;" ::: "memory")
#define CP_WAIT(n)  asm volatile("cp.async.wait_group %0;" :: "n"(n) : "memory")

__device__ __forceinline__ uint32_t smem_u32(const void* p) {
    uint32_t a;
    asm("{ .reg .u64 t; cvta.to.shared.u64 t, %1; cvt.u32.u64 %0, t; }"
        : "=r"(a) : "l"(p));
    return a;
}

__device__ __forceinline__ float tf32r(float x) {
    float y;
    asm("cvt.rna.tf32.f32 %0, %1;" : "=f"(y) : "f"(x));
    return y;
}

// mma m16n8k8 tf32 -> f32
#define MMA_TF32(c, a0, a1, a2, a3, b0, b1)                                   \
    asm volatile(                                                             \
        "mma.sync.aligned.m16n8k8.row.col.f32.tf32.tf32.f32 "                 \
        "{%0,%1,%2,%3},{%4,%5,%6,%7},{%8,%9},{%0,%1,%2,%3};"                  \
        : "+f"((c)[0]), "+f"((c)[1]), "+f"((c)[2]), "+f"((c)[3])              \
        : "r"(a0), "r"(a1), "r"(a2), "r"(a3), "r"(b0), "r"(b1))

// mma m16n8k16 bf16 -> f32
#define MMA16816(c, a0, a1, a2, a3, b0, b1)                                   \
    asm volatile(                                                             \
        "mma.sync.aligned.m16n8k16.row.col.f32.bf16.bf16.f32 "                \
        "{%0,%1,%2,%3}, {%4,%5,%6,%7}, {%8,%9}, {%0,%1,%2,%3};"               \
        : "+f"((c)[0]), "+f"((c)[1]), "+f"((c)[2]), "+f"((c)[3])              \
        : "r"(a0), "r"(a1), "r"(a2), "r"(a3), "r"(b0), "r"(b1))

// ---------------------------------------------------------------------------
// RoPE tables
// ---------------------------------------------------------------------------
__global__ void rope_table_kernel() {
    int idx = blockIdx.x * 256 + threadIdx.x;
    int pos = idx >> 5;
    int i   = idx & 31;
    float inv = exp2f(-(float)i * 0.4152410118609203f);  // log2(10000)/32
    float ang = (float)pos * inv;
    float s, c;
    sincosf(ang, &s, &c);
    g_cos[idx] = c;
    g_sin[idx] = s;
}

// ---------------------------------------------------------------------------
// tf32 pre-rounding of x and the four weight matrices
// total elems = 4M (x) + 4 x 1M (W) = 8M; 4 per thread
// ---------------------------------------------------------------------------
__global__ void round_kernel(const float* __restrict__ x,
                             const float* __restrict__ wq,
                             const float* __restrict__ wk,
                             const float* __restrict__ wv,
                             const float* __restrict__ wo)
{
    int i4 = (blockIdx.x * 256 + threadIdx.x) * 4;
    const float* src;
    float* dst;
    int off;
    if (i4 < Mn * Dn) {
        src = x; dst = g_xr; off = i4;
    } else {
        int j = i4 - Mn * Dn;
        int w = j >> 20;
        off = j & ((1 << 20) - 1);
        src = (w == 0) ? wq : (w == 1) ? wk : (w == 2) ? wv : wo;
        dst = (w == 0) ? g_wqr : (w == 1) ? g_wkr : (w == 2) ? g_wvr : g_wor;
    }
    float4 v = *(const float4*)(src + off);
    v.x = tf32r(v.x); v.y = tf32r(v.y); v.z = tf32r(v.z); v.w = tf32r(v.w);
    *(float4*)(dst + off) = v;
}

// ---------------------------------------------------------------------------
// Raw-mma tf32 GEMM core. 128x128 tile, BK=32, 2-stage cp.async, LDT=36.
// 8 warps (4m x 2n), warp tile 32x64, acc in regs, register epilogue.
// MODE 0: C = A@W^T + bias (fp32 out)
// MODE 1: QKV fused — blockIdx.x selects {q,k,v} x 8 n-tiles; epilogue does
//         bias + RoPE (q,k) + 0.125 (q) and writes bf16 hi/lo splits.
// ---------------------------------------------------------------------------
#define LDT3 36
#define TILE3 (128 * LDT3)          // floats per operand tile (4608)
#define STG3  (2 * TILE3)           // per stage A+W
#define GSMEM (2 * STG3 * 4)        // 73728 bytes

template<int MODE>
__global__ void __launch_bounds__(256, 2) gemm_mma(
    const float* __restrict__ A,
    const float* __restrict__ W0, const float* __restrict__ W1,
    const float* __restrict__ W2,
    const float* __restrict__ b0p, const float* __restrict__ b1p,
    const float* __restrict__ b2p,
    float* __restrict__ C)
{
    extern __shared__ float smem[];
    const uint32_t sb = smem_u32(smem);
    const int tid = threadIdx.x;
    const int wid = tid >> 5, lane = tid & 31;
    const int g = lane >> 2, tig = lane & 3;
    const int wm = wid & 3, wn = wid >> 2;
    const int m0 = blockIdx.y * 128;

    int wsel = 0, n0;
    const float* W;
    const float* bias;
    if (MODE == 1) {
        wsel = blockIdx.x >> 3;
        n0 = (blockIdx.x & 7) * 128;
        W    = (wsel == 0) ? W0 : (wsel == 1) ? W1 : W2;
        bias = (wsel == 0) ? b0p : (wsel == 1) ? b1p : b2p;
    } else {
        n0 = blockIdx.x * 128;
        W = W0; bias = b0p;
    }

    auto loadChunk = [&](int c) {
        const int s = c & 1;
        const uint32_t abase = sb + s * STG3 * 4;
        const uint32_t wbase = abase + TILE3 * 4;
        const float* Ab = A + (size_t)m0 * Dn + c * 32;
        const float* Wb = W + (size_t)n0 * Dn + c * 32;
        #pragma unroll
        for (int i = 0; i < 4; ++i) {
            int task = tid + i * 256;       // 1024 tasks per operand
            int row = task >> 3;
            int q   = task & 7;
            uint32_t off = (uint32_t)(row * 144 + q * 16);
            cpa16(abase + off, Ab + (size_t)row * Dn + q * 4);
            cpa16(wbase + off, Wb + (size_t)row * Dn + q * 4);
        }
    };

    float acc[2][8][4];
    #pragma unroll
    for (int mi = 0; mi < 2; ++mi)
        #pragma unroll
        for (int nj = 0; nj < 8; ++nj)
            #pragma unroll
            for (int e = 0; e < 4; ++e) acc[mi][nj][e] = 0.0f;

    loadChunk(0); CP_COMMIT();

    for (int c = 0; c < 32; ++c) {
        if (c + 1 < 32) { loadChunk(c + 1); CP_COMMIT(); CP_WAIT(1); }
        else            { CP_WAIT(0); }
        __syncthreads();

        const uint32_t* Asu = (const uint32_t*)(smem + (c & 1) * STG3);
        const uint32_t* Wsu = Asu + TILE3;

        #pragma unroll
        for (int k8 = 0; k8 < 4; ++k8) {
            const int k0 = k8 * 8 + tig;
            uint32_t a[2][4];
            #pragma unroll
            for (int mi = 0; mi < 2; ++mi) {
                const int rb = (wm * 32 + mi * 16 + g) * LDT3 + k0;
                a[mi][0] = Asu[rb];
                a[mi][1] = Asu[rb + 8 * LDT3];
                a[mi][2] = Asu[rb + 4];
                a[mi][3] = Asu[rb + 8 * LDT3 + 4];
            }
            #pragma unroll
            for (int nj = 0; nj < 8; ++nj) {
                const int nb = (wn * 64 + nj * 8 + g) * LDT3 + k0;
                uint32_t bb0 = Wsu[nb];
                uint32_t bb1 = Wsu[nb + 4];
                MMA_TF32(acc[0][nj], a[0][0], a[0][1], a[0][2], a[0][3], bb0, bb1);
                MMA_TF32(acc[1][nj], a[1][0], a[1][1], a[1][2], a[1][3], bb0, bb1);
            }
        }
        __syncthreads();
    }

    // ---- register epilogue ----
    #pragma unroll
    for (int mi = 0; mi < 2; ++mi) {
        #pragma unroll
        for (int nj = 0; nj < 8; ++nj) {
            const int col_l = wn * 64 + nj * 8 + 2 * tig;
            #pragma unroll
            for (int e2 = 0; e2 < 2; ++e2) {
                const int row = m0 + wm * 32 + mi * 16 + g + e2 * 8;
                float v0 = acc[mi][nj][e2 * 2 + 0] + __ldg(&bias[col_l]);
                float v1 = acc[mi][nj][e2 * 2 + 1] + __ldg(&bias[col_l + 1]);
                if (MODE == 0) {
                    *(float2*)(C + (size_t)row * Dn + n0 + col_l) =
                        make_float2(v0, v1);
                } else {
                    if (wsel < 2) {   // RoPE for q,k
                        const int pos = row & (Sn - 1);
                        const int i0 = (col_l & 63) >> 1;
                        float cc = g_cos[pos * 32 + i0];
                        float ss = g_sin[pos * 32 + i0];
                        float o0 = v0 * cc - v1 * ss;
                        float o1 = v0 * ss + v1 * cc;
                        v0 = o0; v1 = o1;
                    }
                    if (wsel == 0) { v0 *= 0.125f; v1 *= 0.125f; }
                    __nv_bfloat16 h0 = __float2bfloat16(v0);
                    __nv_bfloat16 h1 = __float2bfloat16(v1);
                    __nv_bfloat162 hh; hh.x = h0; hh.y = h1;
                    __nv_bfloat162 ll;
                    ll.x = __float2bfloat16(v0 - __bfloat162float(h0));
                    ll.y = __float2bfloat16(v1 - __bfloat162float(h1));
                    const size_t idx = (size_t)row * Dn + n0 + col_l;
                    __nv_bfloat16* dh = (wsel == 0) ? g_qh : (wsel == 1) ? g_kh : g_vh;
                    __nv_bfloat16* dl = (wsel == 0) ? g_ql : (wsel == 1) ? g_kl : g_vl;
                    *(__nv_bfloat162*)(dh + idx) = hh;
                    *(__nv_bfloat162*)(dl + idx) = ll;
                }
            }
        }
    }
}

// ---------------------------------------------------------------------------
// Flash attention: tensor-core bf16x3, 128 q-rows per CTA, k-tile 64.
// Epilogue writes tf32-rounded fp32 (feeds the O projection directly).
// ---------------------------------------------------------------------------
#define SLDS 66
#define SLD  72
#define ATT_SMEM 109056

__global__ void __launch_bounds__(256) attn2(const int* __restrict__ eff,
                                             float* __restrict__ Outp)
{
    extern __shared__ char sm[];
    float*         Ss = (float*)sm;
    __nv_bfloat16* Ph = (__nv_bfloat16*)(sm + 33792);
    __nv_bfloat16* Pl = (__nv_bfloat16*)(sm + 52224);
    __nv_bfloat16* Kh = (__nv_bfloat16*)(sm + 70656);
    __nv_bfloat16* Kl = (__nv_bfloat16*)(sm + 79872);
    __nv_bfloat16* Vh = (__nv_bfloat16*)(sm + 89088);
    __nv_bfloat16* Vl = (__nv_bfloat16*)(sm + 98304);
    float*         Sm = (float*)(sm + 107520);
    float*         Sl = (float*)(sm + 108032);
    float*         Sa = (float*)(sm + 108544);

    const int t = threadIdx.x, w = t >> 5, lane = t & 31;
    const int g = lane >> 2, tig = lane & 3;
    const int q0 = ((int)gridDim.x - 1 - (int)blockIdx.x) * 128;
    const int h = blockIdx.y, b = blockIdx.z;
    const int kend = Sn - eff[b];

    const size_t bofs = (size_t)b * Sn * Dn + h * HDn;

    uint32_t qhf[4][4], qlf[4][4];
    {
        const __nv_bfloat16* bh = g_qh + bofs + (size_t)(q0 + w * 16 + g) * Dn;
        const __nv_bfloat16* bl = g_ql + bofs + (size_t)(q0 + w * 16 + g) * Dn;
        #pragma unroll
        for (int ks = 0; ks < 4; ++ks) {
            int d0 = ks * 16 + 2 * tig;
            qhf[ks][0] = *(const uint32_t*)(bh + d0);
            qhf[ks][1] = *(const uint32_t*)(bh + 8 * (size_t)Dn + d0);
            qhf[ks][2] = *(const uint32_t*)(bh + d0 + 8);
            qhf[ks][3] = *(const uint32_t*)(bh + 8 * (size_t)Dn + d0 + 8);
            qlf[ks][0] = *(const uint32_t*)(bl + d0);
            qlf[ks][1] = *(const uint32_t*)(bl + 8 * (size_t)Dn + d0);
            qlf[ks][2] = *(const uint32_t*)(bl + d0 + 8);
            qlf[ks][3] = *(const uint32_t*)(bl + 8 * (size_t)Dn + d0 + 8);
        }
    }

    float oc[8][4];
    #pragma unroll
    for (int n = 0; n < 8; ++n) { oc[n][0]=0.f; oc[n][1]=0.f; oc[n][2]=0.f; oc[n][3]=0.f; }

    if (t < 128) { Sm[t] = -1e30f; Sl[t] = 0.f; }
    __syncthreads();

    const int klimit = min(q0 + 128, kend);
    const int nt = (klimit + 63) >> 6;

    for (int tile = 0; tile < nt; ++tile) {
        const int j0 = tile * 64;
        const __nv_bfloat16* KgH = g_kh + bofs + (size_t)j0 * Dn;
        const __nv_bfloat16* KgL = g_kl + bofs + (size_t)j0 * Dn;
        const __nv_bfloat16* VgH = g_vh + bofs + (size_t)j0 * Dn;
        const __nv_bfloat16* VgL = g_vl + bofs + (size_t)j0 * Dn;

        #pragma unroll
        for (int i2 = 0; i2 < 8; ++i2) {
            int task = t + i2 * 256;
            int kr = task >> 5;
            int d0 = (task & 31) * 2;
            *(uint32_t*)&Kh[kr * SLD + d0] = *(const uint32_t*)(KgH + (size_t)kr * Dn + d0);
            *(uint32_t*)&Kl[kr * SLD + d0] = *(const uint32_t*)(KgL + (size_t)kr * Dn + d0);
            __nv_bfloat162 vh2 = *(const __nv_bfloat162*)(VgH + (size_t)kr * Dn + d0);
            Vh[d0 * SLD + kr]       = vh2.x;
            Vh[(d0 + 1) * SLD + kr] = vh2.y;
            __nv_bfloat162 vl2 = *(const __nv_bfloat162*)(VgL + (size_t)kr * Dn + d0);
            Vl[d0 * SLD + kr]       = vl2.x;
            Vl[(d0 + 1) * SLD + kr] = vl2.y;
        }
        __syncthreads();

        #pragma unroll
        for (int n = 0; n < 8; ++n) {
            float c[4] = {0.f, 0.f, 0.f, 0.f};
            const int krow = (n * 8 + g) * SLD;
            #pragma unroll
            for (int ks = 0; ks < 4; ++ks) {
                int dd = ks * 16 + 2 * tig;
                uint32_t b0h = *(uint32_t*)&Kh[krow + dd];
                uint32_t b1h = *(uint32_t*)&Kh[krow + dd + 8];
                uint32_t b0l = *(uint32_t*)&Kl[krow + dd];
                uint32_t b1l = *(uint32_t*)&Kl[krow + dd + 8];
                MMA16816(c, qhf[ks][0], qhf[ks][1], qhf[ks][2], qhf[ks][3], b0h, b1h);
                MMA16816(c, qhf[ks][0], qhf[ks][1], qhf[ks][2], qhf[ks][3], b0l, b1l);
                MMA16816(c, qlf[ks][0], qlf[ks][1], qlf[ks][2], qlf[ks][3], b0h, b1h);
            }
            int rr = w * 16 + g, cc = n * 8 + 2 * tig;
            *(float2*)&Ss[rr * SLDS + cc]       = make_float2(c[0], c[1]);
            *(float2*)&Ss[(rr + 8) * SLDS + cc] = make_float2(c[2], c[3]);
        }
        __syncthreads();

        {
            const int r = t >> 1, half = t & 1;
            const int rowg = q0 + r;
            const int cbase = half * 32;
            float pv[32];
            float mx = -1e30f;
            #pragma unroll
            for (int j = 0; j < 32; ++j) {
                int cg = j0 + cbase + j;
                float s = Ss[r * SLDS + cbase + j];
                bool ok = (cg <= rowg) && (cg < kend);
                float sv = ok ? s : -1e30f;
                pv[j] = sv;
                mx = fmaxf(mx, sv);
            }
            mx = fmaxf(mx, __shfl_xor_sync(0xffffffffu, mx, 1));
            float mold = Sm[r];
            float nm = fmaxf(mold, mx);
            float al = __expf(mold - nm);
            float sum = 0.f;
            #pragma unroll
            for (int j = 0; j < 32; ++j) {
                float p = __expf(pv[j] - nm);
                pv[j] = p;
                sum += p;
            }
            sum += __shfl_xor_sync(0xffffffffu, sum, 1);
            if (half == 0) {
                Sm[r] = nm;
                Sl[r] = Sl[r] * al + sum;
                Sa[r] = al;
            }
            #pragma unroll
            for (int j = 0; j < 32; j += 2) {
                __nv_bfloat16 h0 = __float2bfloat16(pv[j]);
                __nv_bfloat16 h1 = __float2bfloat16(pv[j + 1]);
                __nv_bfloat162 hh; hh.x = h0; hh.y = h1;
                *(__nv_bfloat162*)&Ph[r * SLD + cbase + j] = hh;
                __nv_bfloat162 ll;
                ll.x = __float2bfloat16(pv[j]     - __bfloat162float(h0));
                ll.y = __float2bfloat16(pv[j + 1] - __bfloat162float(h1));
                *(__nv_bfloat162*)&Pl[r * SLD + cbase + j] = ll;
            }
        }
        __syncthreads();

        {
            float aA = Sa[w * 16 + g];
            float aB = Sa[w * 16 + g + 8];
            #pragma unroll
            for (int n = 0; n < 8; ++n) {
                oc[n][0] *= aA; oc[n][1] *= aA;
                oc[n][2] *= aB; oc[n][3] *= aB;
            }
            const int pr = (w * 16 + g) * SLD;
            #pragma unroll
            for (int ks = 0; ks < 4; ++ks) {
                int kk = ks * 16 + 2 * tig;
                uint32_t ah0 = *(uint32_t*)&Ph[pr + kk];
                uint32_t ah1 = *(uint32_t*)&Ph[pr + 8 * SLD + kk];
                uint32_t ah2 = *(uint32_t*)&Ph[pr + kk + 8];
                uint32_t ah3 = *(uint32_t*)&Ph[pr + 8 * SLD + kk + 8];
                uint32_t al0 = *(uint32_t*)&Pl[pr + kk];
                uint32_t al1 = *(uint32_t*)&Pl[pr + 8 * SLD + kk];
                uint32_t al2 = *(uint32_t*)&Pl[pr + kk + 8];
                uint32_t al3 = *(uint32_t*)&Pl[pr + 8 * SLD + kk + 8];
                #pragma unroll
                for (int n = 0; n < 8; ++n) {
                    const int vrow = (n * 8 + g) * SLD;
                    uint32_t b0h = *(uint32_t*)&Vh[vrow + kk];
                    uint32_t b1h = *(uint32_t*)&Vh[vrow + kk + 8];
                    uint32_t b0l = *(uint32_t*)&Vl[vrow + kk];
                    uint32_t b1l = *(uint32_t*)&Vl[vrow + kk + 8];
                    MMA16816(oc[n], ah0, ah1, ah2, ah3, b0h, b1h);
                    MMA16816(oc[n], ah0, ah1, ah2, ah3, b0l, b1l);
                    MMA16816(oc[n], al0, al1, al2, al3, b0h, b1h);
                }
            }
        }
        __syncthreads();
    }

    float invA = 1.f / Sl[w * 16 + g];
    float invB = 1.f / Sl[w * 16 + g + 8];
    float* Ob = Outp + bofs + (size_t)(q0 + w * 16 + g) * Dn;
    #pragma unroll
    for (int n = 0; n < 8; ++n) {
        int cc = n * 8 + 2 * tig;
        *(float2*)&Ob[cc] =
            make_float2(tf32r(oc[n][0] * invA), tf32r(oc[n][1] * invA));
        *(float2*)(Ob + 8 * (size_t)Dn + cc) =
            make_float2(tf32r(oc[n][2] * invB), tf32r(oc[n][3] * invB));
    }
}

// ---------------------------------------------------------------------------
extern "C" void kernel_launch(void* const* d_in, const int* in_sizes, int n_in,
                              void* d_out, int out_size)
{
    const float* x   = (const float*)d_in[0];
    const int*   eff = (const int*)d_in[1];
    const float* Wq  = (const float*)d_in[2];
    const float* bq  = (const float*)d_in[3];
    const float* Wk  = (const float*)d_in[4];
    const float* bk  = (const float*)d_in[5];
    const float* Wv  = (const float*)d_in[6];
    const float* bv  = (const float*)d_in[7];
    const float* Wo  = (const float*)d_in[8];
    const float* bo  = (const float*)d_in[9];
    float* out = (float*)d_out;

    float *att, *xr, *wqr, *wkr, *wvr, *wor;
    cudaGetSymbolAddress((void**)&att, g_att);
    cudaGetSymbolAddress((void**)&xr,  g_xr);
    cudaGetSymbolAddress((void**)&wqr, g_wqr);
    cudaGetSymbolAddress((void**)&wkr, g_wkr);
    cudaGetSymbolAddress((void**)&wvr, g_wvr);
    cudaGetSymbolAddress((void**)&wor, g_wor);

    cudaFuncSetAttribute(gemm_mma<0>,
                         cudaFuncAttributeMaxDynamicSharedMemorySize, GSMEM);
    cudaFuncSetAttribute(gemm_mma<1>,
                         cudaFuncAttributeMaxDynamicSharedMemorySize, GSMEM);
    cudaFuncSetAttribute(attn2,
                         cudaFuncAttributeMaxDynamicSharedMemorySize, ATT_SMEM);

    rope_table_kernel<<<(Sn * 32) / 256, 256>>>();
    round_kernel<<<(Mn * Dn + 4 * Dn * Dn) / 1024, 256>>>(x, Wq, Wk, Wv, Wo);

    // fused QKV projection (24 n-tiles x 32 m-tiles)
    gemm_mma<1><<<dim3(24, 32), 256, GSMEM>>>(xr, wqr, wkr, wvr,
                                              bq, bk, bv, nullptr);

    attn2<<<dim3(Sn / 128, Hn, Bn), 256, ATT_SMEM>>>(eff, att);

    // O projection
    gemm_mma<0><<<dim3(8, 32), 256, GSMEM>>>(att, wor, nullptr, nullptr,
                                             bo, nullptr, nullptr, out);
}

// round 6
// speedup vs baseline: 2.6993x; 1.1007x over previous
#include <cuda_runtime.h>
#include <cuda_bf16.h>
#include <cstdint>

#define Bn 2
#define Sn 2048
#define Dn 1024
#define Hn 16
#define HDn 64
#define Mn (Bn*Sn)

// Scratch (allocation-free rule: device globals)
__device__ float g_att[Mn*Dn];
__device__ float g_xr[Mn*Dn];                 // tf32-rounded x
__device__ float g_wqr[Dn*Dn], g_wkr[Dn*Dn], g_wvr[Dn*Dn], g_wor[Dn*Dn];
__device__ float g_cos[Sn*32];
__device__ float g_sin[Sn*32];
__device__ __nv_bfloat16 g_qh[Mn*Dn], g_ql[Mn*Dn];
__device__ __nv_bfloat16 g_kh[Mn*Dn], g_kl[Mn*Dn];
__device__ __nv_bfloat16 g_vh[Mn*Dn], g_vl[Mn*Dn];

// ---------------------------------------------------------------------------
__device__ __forceinline__ void cpa16(uint32_t dst, const void* src) {
    asm volatile("cp.async.cg.shared.global [%0], [%1], 16;" :: "r"(dst), "l"(src));
}
#define CP_COMMIT() asm volatile("cp.async.commit_group;" ::: "memory")
#define CP_WAIT(n)  asm volatile("cp.async.wait_group %0;" :: "n"(n) : "memory")

__device__ __forceinline__ uint32_t smem_u32(const void* p) {
    uint32_t a;
    asm("{ .reg .u64 t; cvta.to.shared.u64 t, %1; cvt.u32.u64 %0, t; }"
        : "=r"(a) : "l"(p));
    return a;
}

__device__ __forceinline__ float tf32r(float x) {
    float y;
    asm("cvt.rna.tf32.f32 %0, %1;" : "=f"(y) : "f"(x));
    return y;
}

// mma m16n8k8 tf32 -> f32
#define MMA_TF32(c, a0, a1, a2, a3, b0, b1)                                   \
    asm volatile(                                                             \
        "mma.sync.aligned.m16n8k8.row.col.f32.tf32.tf32.f32 "                 \
        "{%0,%1,%2,%3},{%4,%5,%6,%7},{%8,%9},{%0,%1,%2,%3};"                  \
        : "+f"((c)[0]), "+f"((c)[1]), "+f"((c)[2]), "+f"((c)[3])              \
        : "r"(a0), "r"(a1), "r"(a2), "r"(a3), "r"(b0), "r"(b1))

// mma m16n8k16 bf16 -> f32
#define MMA16816(c, a0, a1, a2, a3, b0, b1)                                   \
    asm volatile(                                                             \
        "mma.sync.aligned.m16n8k16.row.col.f32.bf16.bf16.f32 "                \
        "{%0,%1,%2,%3}, {%4,%5,%6,%7}, {%8,%9}, {%0,%1,%2,%3};"               \
        : "+f"((c)[0]), "+f"((c)[1]), "+f"((c)[2]), "+f"((c)[3])              \
        : "r"(a0), "r"(a1), "r"(a2), "r"(a3), "r"(b0), "r"(b1))

__device__ __forceinline__ uint32_t pack_hi(float a, float b,
                                            float& ra, float& rb) {
    __nv_bfloat16 h0 = __float2bfloat16(a);
    __nv_bfloat16 h1 = __float2bfloat16(b);
    ra = a - __bfloat162float(h0);
    rb = b - __bfloat162float(h1);
    __nv_bfloat162 hh; hh.x = h0; hh.y = h1;
    return *(uint32_t*)&hh;
}
__device__ __forceinline__ uint32_t pack_bf(float a, float b) {
    __nv_bfloat162 hh;
    hh.x = __float2bfloat16(a);
    hh.y = __float2bfloat16(b);
    return *(uint32_t*)&hh;
}

// ---------------------------------------------------------------------------
// RoPE tables
// ---------------------------------------------------------------------------
__global__ void rope_table_kernel() {
    int idx = blockIdx.x * 256 + threadIdx.x;
    int pos = idx >> 5;
    int i   = idx & 31;
    float inv = exp2f(-(float)i * 0.4152410118609203f);  // log2(10000)/32
    float ang = (float)pos * inv;
    float s, c;
    sincosf(ang, &s, &c);
    g_cos[idx] = c;
    g_sin[idx] = s;
}

// ---------------------------------------------------------------------------
// tf32 pre-rounding of x and the four weight matrices
// ---------------------------------------------------------------------------
__global__ void round_kernel(const float* __restrict__ x,
                             const float* __restrict__ wq,
                             const float* __restrict__ wk,
                             const float* __restrict__ wv,
                             const float* __restrict__ wo)
{
    int i4 = (blockIdx.x * 256 + threadIdx.x) * 4;
    const float* src;
    float* dst;
    int off;
    if (i4 < Mn * Dn) {
        src = x; dst = g_xr; off = i4;
    } else {
        int j = i4 - Mn * Dn;
        int w = j >> 20;
        off = j & ((1 << 20) - 1);
        src = (w == 0) ? wq : (w == 1) ? wk : (w == 2) ? wv : wo;
        dst = (w == 0) ? g_wqr : (w == 1) ? g_wkr : (w == 2) ? g_wvr : g_wor;
    }
    float4 v = *(const float4*)(src + off);
    v.x = tf32r(v.x); v.y = tf32r(v.y); v.z = tf32r(v.z); v.w = tf32r(v.w);
    *(float4*)(dst + off) = v;
}

// ---------------------------------------------------------------------------
// Raw-mma tf32 GEMM (unchanged from R5)
// ---------------------------------------------------------------------------
#define LDT3 36
#define TILE3 (128 * LDT3)
#define STG3  (2 * TILE3)
#define GSMEM (2 * STG3 * 4)        // 73728 bytes

template<int MODE>
__global__ void __launch_bounds__(256, 2) gemm_mma(
    const float* __restrict__ A,
    const float* __restrict__ W0, const float* __restrict__ W1,
    const float* __restrict__ W2,
    const float* __restrict__ b0p, const float* __restrict__ b1p,
    const float* __restrict__ b2p,
    float* __restrict__ C)
{
    extern __shared__ float smem[];
    const uint32_t sb = smem_u32(smem);
    const int tid = threadIdx.x;
    const int wid = tid >> 5, lane = tid & 31;
    const int g = lane >> 2, tig = lane & 3;
    const int wm = wid & 3, wn = wid >> 2;
    const int m0 = blockIdx.y * 128;

    int wsel = 0, n0;
    const float* W;
    const float* bias;
    if (MODE == 1) {
        wsel = blockIdx.x >> 3;
        n0 = (blockIdx.x & 7) * 128;
        W    = (wsel == 0) ? W0 : (wsel == 1) ? W1 : W2;
        bias = (wsel == 0) ? b0p : (wsel == 1) ? b1p : b2p;
    } else {
        n0 = blockIdx.x * 128;
        W = W0; bias = b0p;
    }

    auto loadChunk = [&](int c) {
        const int s = c & 1;
        const uint32_t abase = sb + s * STG3 * 4;
        const uint32_t wbase = abase + TILE3 * 4;
        const float* Ab = A + (size_t)m0 * Dn + c * 32;
        const float* Wb = W + (size_t)n0 * Dn + c * 32;
        #pragma unroll
        for (int i = 0; i < 4; ++i) {
            int task = tid + i * 256;
            int row = task >> 3;
            int q   = task & 7;
            uint32_t off = (uint32_t)(row * 144 + q * 16);
            cpa16(abase + off, Ab + (size_t)row * Dn + q * 4);
            cpa16(wbase + off, Wb + (size_t)row * Dn + q * 4);
        }
    };

    float acc[2][8][4];
    #pragma unroll
    for (int mi = 0; mi < 2; ++mi)
        #pragma unroll
        for (int nj = 0; nj < 8; ++nj)
            #pragma unroll
            for (int e = 0; e < 4; ++e) acc[mi][nj][e] = 0.0f;

    loadChunk(0); CP_COMMIT();

    for (int c = 0; c < 32; ++c) {
        if (c + 1 < 32) { loadChunk(c + 1); CP_COMMIT(); CP_WAIT(1); }
        else            { CP_WAIT(0); }
        __syncthreads();

        const uint32_t* Asu = (const uint32_t*)(smem + (c & 1) * STG3);
        const uint32_t* Wsu = Asu + TILE3;

        #pragma unroll
        for (int k8 = 0; k8 < 4; ++k8) {
            const int k0 = k8 * 8 + tig;
            uint32_t a[2][4];
            #pragma unroll
            for (int mi = 0; mi < 2; ++mi) {
                const int rb = (wm * 32 + mi * 16 + g) * LDT3 + k0;
                a[mi][0] = Asu[rb];
                a[mi][1] = Asu[rb + 8 * LDT3];
                a[mi][2] = Asu[rb + 4];
                a[mi][3] = Asu[rb + 8 * LDT3 + 4];
            }
            #pragma unroll
            for (int nj = 0; nj < 8; ++nj) {
                const int nb = (wn * 64 + nj * 8 + g) * LDT3 + k0;
                uint32_t bb0 = Wsu[nb];
                uint32_t bb1 = Wsu[nb + 4];
                MMA_TF32(acc[0][nj], a[0][0], a[0][1], a[0][2], a[0][3], bb0, bb1);
                MMA_TF32(acc[1][nj], a[1][0], a[1][1], a[1][2], a[1][3], bb0, bb1);
            }
        }
        __syncthreads();
    }

    #pragma unroll
    for (int mi = 0; mi < 2; ++mi) {
        #pragma unroll
        for (int nj = 0; nj < 8; ++nj) {
            const int col_l = wn * 64 + nj * 8 + 2 * tig;
            #pragma unroll
            for (int e2 = 0; e2 < 2; ++e2) {
                const int row = m0 + wm * 32 + mi * 16 + g + e2 * 8;
                float v0 = acc[mi][nj][e2 * 2 + 0] + __ldg(&bias[col_l]);
                float v1 = acc[mi][nj][e2 * 2 + 1] + __ldg(&bias[col_l + 1]);
                if (MODE == 0) {
                    *(float2*)(C + (size_t)row * Dn + n0 + col_l) =
                        make_float2(v0, v1);
                } else {
                    if (wsel < 2) {
                        const int pos = row & (Sn - 1);
                        const int i0 = (col_l & 63) >> 1;
                        float cc = g_cos[pos * 32 + i0];
                        float ss = g_sin[pos * 32 + i0];
                        float o0 = v0 * cc - v1 * ss;
                        float o1 = v0 * ss + v1 * cc;
                        v0 = o0; v1 = o1;
                    }
                    if (wsel == 0) { v0 *= 0.125f; v1 *= 0.125f; }
                    float r0, r1;
                    uint32_t hh = pack_hi(v0, v1, r0, r1);
                    uint32_t ll = pack_bf(r0, r1);
                    const size_t idx = (size_t)row * Dn + n0 + col_l;
                    __nv_bfloat16* dh = (wsel == 0) ? g_qh : (wsel == 1) ? g_kh : g_vh;
                    __nv_bfloat16* dl = (wsel == 0) ? g_ql : (wsel == 1) ? g_kl : g_vl;
                    *(uint32_t*)(dh + idx) = hh;
                    *(uint32_t*)(dl + idx) = ll;
                }
            }
        }
    }
}

// ---------------------------------------------------------------------------
// Flash attention v3: fully register-resident softmax.
// 128 q-rows per CTA, k-tile 64, 8 warps x 16 rows, 2 CTAs/SM.
// smem: Kh/Kl [64][72] bf16, VhT/VlT [64d][72k] bf16  (36864 B)
// ---------------------------------------------------------------------------
#define KLD 72
#define ATT_SMEM 36864

__global__ void __launch_bounds__(256, 2) attn3(const int* __restrict__ eff,
                                                float* __restrict__ Outp)
{
    extern __shared__ char sm[];
    __nv_bfloat16* Kh = (__nv_bfloat16*)sm;
    __nv_bfloat16* Kl = (__nv_bfloat16*)(sm + 9216);
    __nv_bfloat16* Vh = (__nv_bfloat16*)(sm + 18432);
    __nv_bfloat16* Vl = (__nv_bfloat16*)(sm + 27648);

    const int t = threadIdx.x, w = t >> 5, lane = t & 31;
    const int g = lane >> 2, tig = lane & 3;
    const int q0 = ((int)gridDim.x - 1 - (int)blockIdx.x) * 128;
    const int h = blockIdx.y, b = blockIdx.z;
    const int kend = Sn - eff[b];
    const size_t bofs = (size_t)b * Sn * Dn + h * HDn;

    const int row0 = q0 + w * 16 + g;
    const int row1 = row0 + 8;

    // --- Q fragments (hi/lo) in registers ---
    uint32_t qhf[4][4], qlf[4][4];
    {
        const __nv_bfloat16* bh = g_qh + bofs + (size_t)row0 * Dn;
        const __nv_bfloat16* bl = g_ql + bofs + (size_t)row0 * Dn;
        #pragma unroll
        for (int ks = 0; ks < 4; ++ks) {
            int d0 = ks * 16 + 2 * tig;
            qhf[ks][0] = *(const uint32_t*)(bh + d0);
            qhf[ks][1] = *(const uint32_t*)(bh + 8 * (size_t)Dn + d0);
            qhf[ks][2] = *(const uint32_t*)(bh + d0 + 8);
            qhf[ks][3] = *(const uint32_t*)(bh + 8 * (size_t)Dn + d0 + 8);
            qlf[ks][0] = *(const uint32_t*)(bl + d0);
            qlf[ks][1] = *(const uint32_t*)(bl + 8 * (size_t)Dn + d0);
            qlf[ks][2] = *(const uint32_t*)(bl + d0 + 8);
            qlf[ks][3] = *(const uint32_t*)(bl + 8 * (size_t)Dn + d0 + 8);
        }
    }

    float oc[8][4];
    #pragma unroll
    for (int n = 0; n < 8; ++n) { oc[n][0]=0.f; oc[n][1]=0.f; oc[n][2]=0.f; oc[n][3]=0.f; }
    float m0r = -1e30f, m1r = -1e30f, l0r = 0.f, l1r = 0.f;

    const int klimit = min(q0 + 128, kend);
    const int nt = (klimit + 63) >> 6;

    for (int tile = 0; tile < nt; ++tile) {
        const int j0 = tile * 64;
        const __nv_bfloat16* KgH = g_kh + bofs + (size_t)j0 * Dn;
        const __nv_bfloat16* KgL = g_kl + bofs + (size_t)j0 * Dn;
        const __nv_bfloat16* VgH = g_vh + bofs + (size_t)j0 * Dn;
        const __nv_bfloat16* VgL = g_vl + bofs + (size_t)j0 * Dn;

        #pragma unroll
        for (int i2 = 0; i2 < 8; ++i2) {
            int task = t + i2 * 256;
            int kr = task >> 5;
            int d0 = (task & 31) * 2;
            *(uint32_t*)&Kh[kr * KLD + d0] = *(const uint32_t*)(KgH + (size_t)kr * Dn + d0);
            *(uint32_t*)&Kl[kr * KLD + d0] = *(const uint32_t*)(KgL + (size_t)kr * Dn + d0);
            __nv_bfloat162 vh2 = *(const __nv_bfloat162*)(VgH + (size_t)kr * Dn + d0);
            Vh[d0 * KLD + kr]       = vh2.x;
            Vh[(d0 + 1) * KLD + kr] = vh2.y;
            __nv_bfloat162 vl2 = *(const __nv_bfloat162*)(VgL + (size_t)kr * Dn + d0);
            Vl[d0 * KLD + kr]       = vl2.x;
            Vl[(d0 + 1) * KLD + kr] = vl2.y;
        }
        __syncthreads();

        // --- S = Q K^T (bf16x3), kept in registers ---
        float sc[8][4];
        #pragma unroll
        for (int n = 0; n < 8; ++n) {
            float c[4] = {0.f, 0.f, 0.f, 0.f};
            const int krow = (n * 8 + g) * KLD;
            #pragma unroll
            for (int ks = 0; ks < 4; ++ks) {
                int dd = ks * 16 + 2 * tig;
                uint32_t b0h = *(uint32_t*)&Kh[krow + dd];
                uint32_t b1h = *(uint32_t*)&Kh[krow + dd + 8];
                uint32_t b0l = *(uint32_t*)&Kl[krow + dd];
                uint32_t b1l = *(uint32_t*)&Kl[krow + dd + 8];
                MMA16816(c, qhf[ks][0], qhf[ks][1], qhf[ks][2], qhf[ks][3], b0h, b1h);
                MMA16816(c, qhf[ks][0], qhf[ks][1], qhf[ks][2], qhf[ks][3], b0l, b1l);
                MMA16816(c, qlf[ks][0], qlf[ks][1], qlf[ks][2], qlf[ks][3], b0h, b1h);
            }
            sc[n][0] = c[0]; sc[n][1] = c[1]; sc[n][2] = c[2]; sc[n][3] = c[3];
        }

        // --- mask + register online softmax (row = 4 tig lanes) ---
        float mx0 = -1e30f, mx1 = -1e30f;
        #pragma unroll
        for (int n = 0; n < 8; ++n) {
            int col = j0 + n * 8 + 2 * tig;
            sc[n][0] = (col     <= row0 && col     < kend) ? sc[n][0] : -1e30f;
            sc[n][1] = (col + 1 <= row0 && col + 1 < kend) ? sc[n][1] : -1e30f;
            sc[n][2] = (col     <= row1 && col     < kend) ? sc[n][2] : -1e30f;
            sc[n][3] = (col + 1 <= row1 && col + 1 < kend) ? sc[n][3] : -1e30f;
            mx0 = fmaxf(mx0, fmaxf(sc[n][0], sc[n][1]));
            mx1 = fmaxf(mx1, fmaxf(sc[n][2], sc[n][3]));
        }
        mx0 = fmaxf(mx0, __shfl_xor_sync(0xffffffffu, mx0, 1));
        mx0 = fmaxf(mx0, __shfl_xor_sync(0xffffffffu, mx0, 2));
        mx1 = fmaxf(mx1, __shfl_xor_sync(0xffffffffu, mx1, 1));
        mx1 = fmaxf(mx1, __shfl_xor_sync(0xffffffffu, mx1, 2));

        float nm0 = fmaxf(m0r, mx0), nm1 = fmaxf(m1r, mx1);
        float al0 = __expf(m0r - nm0), al1 = __expf(m1r - nm1);
        m0r = nm0; m1r = nm1;

        float s0 = 0.f, s1 = 0.f;
        #pragma unroll
        for (int n = 0; n < 8; ++n) {
            sc[n][0] = __expf(sc[n][0] - nm0);
            sc[n][1] = __expf(sc[n][1] - nm0);
            sc[n][2] = __expf(sc[n][2] - nm1);
            sc[n][3] = __expf(sc[n][3] - nm1);
            s0 += sc[n][0] + sc[n][1];
            s1 += sc[n][2] + sc[n][3];
        }
        s0 += __shfl_xor_sync(0xffffffffu, s0, 1);
        s0 += __shfl_xor_sync(0xffffffffu, s0, 2);
        s1 += __shfl_xor_sync(0xffffffffu, s1, 1);
        s1 += __shfl_xor_sync(0xffffffffu, s1, 2);
        l0r = l0r * al0 + s0;
        l1r = l1r * al1 + s1;

        #pragma unroll
        for (int n = 0; n < 8; ++n) {
            oc[n][0] *= al0; oc[n][1] *= al0;
            oc[n][2] *= al1; oc[n][3] *= al1;
        }

        // --- O += P V (bf16x3), P packed from registers ---
        #pragma unroll
        for (int ks = 0; ks < 4; ++ks) {
            float r0, r1;
            uint32_t a0h, a1h, a2h, a3h, a0l, a1l, a2l, a3l;
            a0h = pack_hi(sc[2*ks][0],   sc[2*ks][1],   r0, r1); a0l = pack_bf(r0, r1);
            a1h = pack_hi(sc[2*ks][2],   sc[2*ks][3],   r0, r1); a1l = pack_bf(r0, r1);
            a2h = pack_hi(sc[2*ks+1][0], sc[2*ks+1][1], r0, r1); a2l = pack_bf(r0, r1);
            a3h = pack_hi(sc[2*ks+1][2], sc[2*ks+1][3], r0, r1); a3l = pack_bf(r0, r1);
            const int kk = ks * 16 + 2 * tig;
            #pragma unroll
            for (int n = 0; n < 8; ++n) {
                const int vrow = (n * 8 + g) * KLD;
                uint32_t b0h = *(uint32_t*)&Vh[vrow + kk];
                uint32_t b1h = *(uint32_t*)&Vh[vrow + kk + 8];
                uint32_t b0l = *(uint32_t*)&Vl[vrow + kk];
                uint32_t b1l = *(uint32_t*)&Vl[vrow + kk + 8];
                MMA16816(oc[n], a0h, a1h, a2h, a3h, b0h, b1h);
                MMA16816(oc[n], a0h, a1h, a2h, a3h, b0l, b1l);
                MMA16816(oc[n], a0l, a1l, a2l, a3l, b0h, b1h);
            }
        }
        __syncthreads();
    }

    // --- epilogue: normalize + tf32-round + store ---
    float invA = 1.f / l0r;
    float invB = 1.f / l1r;
    float* Ob = Outp + bofs + (size_t)row0 * Dn;
    #pragma unroll
    for (int n = 0; n < 8; ++n) {
        int cc = n * 8 + 2 * tig;
        *(float2*)&Ob[cc] =
            make_float2(tf32r(oc[n][0] * invA), tf32r(oc[n][1] * invA));
        *(float2*)(Ob + 8 * (size_t)Dn + cc) =
            make_float2(tf32r(oc[n][2] * invB), tf32r(oc[n][3] * invB));
    }
}

// ---------------------------------------------------------------------------
extern "C" void kernel_launch(void* const* d_in, const int* in_sizes, int n_in,
                              void* d_out, int out_size)
{
    const float* x   = (const float*)d_in[0];
    const int*   eff = (const int*)d_in[1];
    const float* Wq  = (const float*)d_in[2];
    const float* bq  = (const float*)d_in[3];
    const float* Wk  = (const float*)d_in[4];
    const float* bk  = (const float*)d_in[5];
    const float* Wv  = (const float*)d_in[6];
    const float* bv  = (const float*)d_in[7];
    const float* Wo  = (const float*)d_in[8];
    const float* bo  = (const float*)d_in[9];
    float* out = (float*)d_out;

    float *att, *xr, *wqr, *wkr, *wvr, *wor;
    cudaGetSymbolAddress((void**)&att, g_att);
    cudaGetSymbolAddress((void**)&xr,  g_xr);
    cudaGetSymbolAddress((void**)&wqr, g_wqr);
    cudaGetSymbolAddress((void**)&wkr, g_wkr);
    cudaGetSymbolAddress((void**)&wvr, g_wvr);
    cudaGetSymbolAddress((void**)&wor, g_wor);

    cudaFuncSetAttribute(gemm_mma<0>,
                         cudaFuncAttributeMaxDynamicSharedMemorySize, GSMEM);
    cudaFuncSetAttribute(gemm_mma<1>,
                         cudaFuncAttributeMaxDynamicSharedMemorySize, GSMEM);
    cudaFuncSetAttribute(attn3,
                         cudaFuncAttributeMaxDynamicSharedMemorySize, ATT_SMEM);

    rope_table_kernel<<<(Sn * 32) / 256, 256>>>();
    round_kernel<<<(Mn * Dn + 4 * Dn * Dn) / 1024, 256>>>(x, Wq, Wk, Wv, Wo);

    // fused QKV projection (24 n-tiles x 32 m-tiles)
    gemm_mma<1><<<dim3(24, 32), 256, GSMEM>>>(xr, wqr, wkr, wvr,
                                              bq, bk, bv, nullptr);

    attn3<<<dim3(Sn / 128, Hn, Bn), 256, ATT_SMEM>>>(eff, att);

    // O projection
    gemm_mma<0><<<dim3(8, 32), 256, GSMEM>>>(att, wor, nullptr, nullptr,
                                             bo, nullptr, nullptr, out);
}

// round 7
// speedup vs baseline: 3.1305x; 1.1598x over previous
#include <cuda_runtime.h>
#include <cuda_bf16.h>
#include <cstdint>

#define Bn 2
#define Sn 2048
#define Dn 1024
#define Hn 16
#define HDn 64
#define Mn (Bn*Sn)

// Scratch (allocation-free rule: device globals)
__device__ float g_att[Mn*Dn];
__device__ float g_xr[Mn*Dn];                 // tf32-rounded x
__device__ float g_wqr[Dn*Dn], g_wkr[Dn*Dn], g_wvr[Dn*Dn], g_wor[Dn*Dn];
__device__ float g_cos[Sn*32];
__device__ float g_sin[Sn*32];
__device__ __nv_bfloat16 g_qh[Mn*Dn], g_ql[Mn*Dn];
__device__ __nv_bfloat16 g_kh[Mn*Dn], g_kl[Mn*Dn];
__device__ __nv_bfloat16 g_vh[Mn*Dn], g_vl[Mn*Dn];

// ---------------------------------------------------------------------------
__device__ __forceinline__ void cpa16(uint32_t dst, const void* src) {
    asm volatile("cp.async.cg.shared.global [%0], [%1], 16;" :: "r"(dst), "l"(src));
}
#define CP_COMMIT() asm volatile("cp.async.commit_group;" ::: "memory")
#define CP_WAIT(n)  asm volatile("cp.async.wait_group %0;" :: "n"(n) : "memory")

__device__ __forceinline__ uint32_t smem_u32(const void* p) {
    uint32_t a;
    asm("{ .reg .u64 t; cvta.to.shared.u64 t, %1; cvt.u32.u64 %0, t; }"
        : "=r"(a) : "l"(p));
    return a;
}

__device__ __forceinline__ float tf32r(float x) {
    float y;
    asm("cvt.rna.tf32.f32 %0, %1;" : "=f"(y) : "f"(x));
    return y;
}

// mma m16n8k8 tf32 -> f32
#define MMA_TF32(c, a0, a1, a2, a3, b0, b1)                                   \
    asm volatile(                                                             \
        "mma.sync.aligned.m16n8k8.row.col.f32.tf32.tf32.f32 "                 \
        "{%0,%1,%2,%3},{%4,%5,%6,%7},{%8,%9},{%0,%1,%2,%3};"                  \
        : "+f"((c)[0]), "+f"((c)[1]), "+f"((c)[2]), "+f"((c)[3])              \
        : "r"(a0), "r"(a1), "r"(a2), "r"(a3), "r"(b0), "r"(b1))

// mma m16n8k16 bf16 -> f32
#define MMA16816(c, a0, a1, a2, a3, b0, b1)                                   \
    asm volatile(                                                             \
        "mma.sync.aligned.m16n8k16.row.col.f32.bf16.bf16.f32 "                \
        "{%0,%1,%2,%3}, {%4,%5,%6,%7}, {%8,%9}, {%0,%1,%2,%3};"               \
        : "+f"((c)[0]), "+f"((c)[1]), "+f"((c)[2]), "+f"((c)[3])              \
        : "r"(a0), "r"(a1), "r"(a2), "r"(a3), "r"(b0), "r"(b1))

#define LDSM_X4(d0,d1,d2,d3,a)                                                \
    asm volatile("ldmatrix.sync.aligned.m8n8.x4.shared.b16 {%0,%1,%2,%3}, [%4];" \
        : "=r"(d0), "=r"(d1), "=r"(d2), "=r"(d3) : "r"(a))
#define LDSM_X4_T(d0,d1,d2,d3,a)                                              \
    asm volatile("ldmatrix.sync.aligned.m8n8.x4.trans.shared.b16 {%0,%1,%2,%3}, [%4];" \
        : "=r"(d0), "=r"(d1), "=r"(d2), "=r"(d3) : "r"(a))

__device__ __forceinline__ uint32_t pack_hi(float a, float b,
                                            float& ra, float& rb) {
    __nv_bfloat16 h0 = __float2bfloat16(a);
    __nv_bfloat16 h1 = __float2bfloat16(b);
    ra = a - __bfloat162float(h0);
    rb = b - __bfloat162float(h1);
    __nv_bfloat162 hh; hh.x = h0; hh.y = h1;
    return *(uint32_t*)&hh;
}
__device__ __forceinline__ uint32_t pack_bf(float a, float b) {
    __nv_bfloat162 hh;
    hh.x = __float2bfloat16(a);
    hh.y = __float2bfloat16(b);
    return *(uint32_t*)&hh;
}

// ---------------------------------------------------------------------------
// RoPE tables
// ---------------------------------------------------------------------------
__global__ void rope_table_kernel() {
    int idx = blockIdx.x * 256 + threadIdx.x;
    int pos = idx >> 5;
    int i   = idx & 31;
    float inv = exp2f(-(float)i * 0.4152410118609203f);  // log2(10000)/32
    float ang = (float)pos * inv;
    float s, c;
    sincosf(ang, &s, &c);
    g_cos[idx] = c;
    g_sin[idx] = s;
}

// ---------------------------------------------------------------------------
// tf32 pre-rounding of x and the four weight matrices
// ---------------------------------------------------------------------------
__global__ void round_kernel(const float* __restrict__ x,
                             const float* __restrict__ wq,
                             const float* __restrict__ wk,
                             const float* __restrict__ wv,
                             const float* __restrict__ wo)
{
    int i4 = (blockIdx.x * 256 + threadIdx.x) * 4;
    const float* src;
    float* dst;
    int off;
    if (i4 < Mn * Dn) {
        src = x; dst = g_xr; off = i4;
    } else {
        int j = i4 - Mn * Dn;
        int w = j >> 20;
        off = j & ((1 << 20) - 1);
        src = (w == 0) ? wq : (w == 1) ? wk : (w == 2) ? wv : wo;
        dst = (w == 0) ? g_wqr : (w == 1) ? g_wkr : (w == 2) ? g_wvr : g_wor;
    }
    float4 v = *(const float4*)(src + off);
    v.x = tf32r(v.x); v.y = tf32r(v.y); v.z = tf32r(v.z); v.w = tf32r(v.w);
    *(float4*)(dst + off) = v;
}

// ---------------------------------------------------------------------------
// Raw-mma tf32 GEMM (unchanged)
// ---------------------------------------------------------------------------
#define LDT3 36
#define TILE3 (128 * LDT3)
#define STG3  (2 * TILE3)
#define GSMEM (2 * STG3 * 4)        // 73728 bytes

template<int MODE>
__global__ void __launch_bounds__(256, 2) gemm_mma(
    const float* __restrict__ A,
    const float* __restrict__ W0, const float* __restrict__ W1,
    const float* __restrict__ W2,
    const float* __restrict__ b0p, const float* __restrict__ b1p,
    const float* __restrict__ b2p,
    float* __restrict__ C)
{
    extern __shared__ float smem[];
    const uint32_t sb = smem_u32(smem);
    const int tid = threadIdx.x;
    const int wid = tid >> 5, lane = tid & 31;
    const int g = lane >> 2, tig = lane & 3;
    const int wm = wid & 3, wn = wid >> 2;
    const int m0 = blockIdx.y * 128;

    int wsel = 0, n0;
    const float* W;
    const float* bias;
    if (MODE == 1) {
        wsel = blockIdx.x >> 3;
        n0 = (blockIdx.x & 7) * 128;
        W    = (wsel == 0) ? W0 : (wsel == 1) ? W1 : W2;
        bias = (wsel == 0) ? b0p : (wsel == 1) ? b1p : b2p;
    } else {
        n0 = blockIdx.x * 128;
        W = W0; bias = b0p;
    }

    auto loadChunk = [&](int c) {
        const int s = c & 1;
        const uint32_t abase = sb + s * STG3 * 4;
        const uint32_t wbase = abase + TILE3 * 4;
        const float* Ab = A + (size_t)m0 * Dn + c * 32;
        const float* Wb = W + (size_t)n0 * Dn + c * 32;
        #pragma unroll
        for (int i = 0; i < 4; ++i) {
            int task = tid + i * 256;
            int row = task >> 3;
            int q   = task & 7;
            uint32_t off = (uint32_t)(row * 144 + q * 16);
            cpa16(abase + off, Ab + (size_t)row * Dn + q * 4);
            cpa16(wbase + off, Wb + (size_t)row * Dn + q * 4);
        }
    };

    float acc[2][8][4];
    #pragma unroll
    for (int mi = 0; mi < 2; ++mi)
        #pragma unroll
        for (int nj = 0; nj < 8; ++nj)
            #pragma unroll
            for (int e = 0; e < 4; ++e) acc[mi][nj][e] = 0.0f;

    loadChunk(0); CP_COMMIT();

    for (int c = 0; c < 32; ++c) {
        if (c + 1 < 32) { loadChunk(c + 1); CP_COMMIT(); CP_WAIT(1); }
        else            { CP_WAIT(0); }
        __syncthreads();

        const uint32_t* Asu = (const uint32_t*)(smem + (c & 1) * STG3);
        const uint32_t* Wsu = Asu + TILE3;

        #pragma unroll
        for (int k8 = 0; k8 < 4; ++k8) {
            const int k0 = k8 * 8 + tig;
            uint32_t a[2][4];
            #pragma unroll
            for (int mi = 0; mi < 2; ++mi) {
                const int rb = (wm * 32 + mi * 16 + g) * LDT3 + k0;
                a[mi][0] = Asu[rb];
                a[mi][1] = Asu[rb + 8 * LDT3];
                a[mi][2] = Asu[rb + 4];
                a[mi][3] = Asu[rb + 8 * LDT3 + 4];
            }
            #pragma unroll
            for (int nj = 0; nj < 8; ++nj) {
                const int nb = (wn * 64 + nj * 8 + g) * LDT3 + k0;
                uint32_t bb0 = Wsu[nb];
                uint32_t bb1 = Wsu[nb + 4];
                MMA_TF32(acc[0][nj], a[0][0], a[0][1], a[0][2], a[0][3], bb0, bb1);
                MMA_TF32(acc[1][nj], a[1][0], a[1][1], a[1][2], a[1][3], bb0, bb1);
            }
        }
        __syncthreads();
    }

    #pragma unroll
    for (int mi = 0; mi < 2; ++mi) {
        #pragma unroll
        for (int nj = 0; nj < 8; ++nj) {
            const int col_l = wn * 64 + nj * 8 + 2 * tig;
            #pragma unroll
            for (int e2 = 0; e2 < 2; ++e2) {
                const int row = m0 + wm * 32 + mi * 16 + g + e2 * 8;
                float v0 = acc[mi][nj][e2 * 2 + 0] + __ldg(&bias[col_l]);
                float v1 = acc[mi][nj][e2 * 2 + 1] + __ldg(&bias[col_l + 1]);
                if (MODE == 0) {
                    *(float2*)(C + (size_t)row * Dn + n0 + col_l) =
                        make_float2(v0, v1);
                } else {
                    if (wsel < 2) {
                        const int pos = row & (Sn - 1);
                        const int i0 = (col_l & 63) >> 1;
                        float cc = g_cos[pos * 32 + i0];
                        float ss = g_sin[pos * 32 + i0];
                        float o0 = v0 * cc - v1 * ss;
                        float o1 = v0 * ss + v1 * cc;
                        v0 = o0; v1 = o1;
                    }
                    if (wsel == 0) { v0 *= 0.125f; v1 *= 0.125f; }
                    float r0, r1;
                    uint32_t hh = pack_hi(v0, v1, r0, r1);
                    uint32_t ll = pack_bf(r0, r1);
                    const size_t idx = (size_t)row * Dn + n0 + col_l;
                    __nv_bfloat16* dh = (wsel == 0) ? g_qh : (wsel == 1) ? g_kh : g_vh;
                    __nv_bfloat16* dl = (wsel == 0) ? g_ql : (wsel == 1) ? g_kl : g_vl;
                    *(uint32_t*)(dh + idx) = hh;
                    *(uint32_t*)(dl + idx) = ll;
                }
            }
        }
    }
}

// ---------------------------------------------------------------------------
// Flash attention v4: ldmatrix fragments + cp.async double-buffered tiles.
// 128 q-rows per CTA, k-tile 64, 8 warps x 16 rows, 2 CTAs/SM.
// Stage layout (bytes, row stride 144): Kh@0, Kl@9216, Vh@18432, Vl@27648
// (K stored [key][d]; V stored [key][d], read via ldmatrix.trans)
// 2 stages x 36864 = 73728 B
// ---------------------------------------------------------------------------
#define ASTG 36864
#define ATT_SMEM (2 * ASTG)

__global__ void __launch_bounds__(256, 2) attn4(const int* __restrict__ eff,
                                                float* __restrict__ Outp)
{
    extern __shared__ char sm[];
    const uint32_t sb = smem_u32(sm);

    const int t = threadIdx.x, w = t >> 5, lane = t & 31;
    const int g = lane >> 2, tig = lane & 3;
    const int part = lane >> 3, r8 = lane & 7;
    const int q0 = ((int)gridDim.x - 1 - (int)blockIdx.x) * 128;
    const int h = blockIdx.y, b = blockIdx.z;
    const int kend = Sn - eff[b];
    const size_t bofs = (size_t)b * Sn * Dn + h * HDn;

    const int row0 = q0 + w * 16 + g;
    const int row1 = row0 + 8;

    // per-lane ldmatrix base addresses (stage-relative)
    // K: lanes 0-7 -> Kh k-lo, 8-15 -> Kh k-hi, 16-23 -> Kl k-lo, 24-31 -> Kl k-hi
    const uint32_t kbase = sb + (part < 2 ? 0u : 9216u)
                         + (uint32_t)r8 * 144 + (uint32_t)(part & 1) * 16;
    // V (trans): lanes 0-7 -> Vh key-lo rows, 8-15 -> Vh key-hi (+8 rows),
    //            16-23 -> Vl key-lo, 24-31 -> Vl key-hi
    const uint32_t vbase = sb + 18432u + (part < 2 ? 0u : 9216u)
                         + (uint32_t)(part & 1) * 1152 + (uint32_t)r8 * 144;

    // --- Q fragments (hi/lo) in registers ---
    uint32_t qhf[4][4], qlf[4][4];
    {
        const __nv_bfloat16* bh = g_qh + bofs + (size_t)row0 * Dn;
        const __nv_bfloat16* bl = g_ql + bofs + (size_t)row0 * Dn;
        #pragma unroll
        for (int ks = 0; ks < 4; ++ks) {
            int d0 = ks * 16 + 2 * tig;
            qhf[ks][0] = *(const uint32_t*)(bh + d0);
            qhf[ks][1] = *(const uint32_t*)(bh + 8 * (size_t)Dn + d0);
            qhf[ks][2] = *(const uint32_t*)(bh + d0 + 8);
            qhf[ks][3] = *(const uint32_t*)(bh + 8 * (size_t)Dn + d0 + 8);
            qlf[ks][0] = *(const uint32_t*)(bl + d0);
            qlf[ks][1] = *(const uint32_t*)(bl + 8 * (size_t)Dn + d0);
            qlf[ks][2] = *(const uint32_t*)(bl + d0 + 8);
            qlf[ks][3] = *(const uint32_t*)(bl + 8 * (size_t)Dn + d0 + 8);
        }
    }

    float oc[8][4];
    #pragma unroll
    for (int n = 0; n < 8; ++n) { oc[n][0]=0.f; oc[n][1]=0.f; oc[n][2]=0.f; oc[n][3]=0.f; }
    float m0r = -1e30f, m1r = -1e30f, l0r = 0.f, l1r = 0.f;

    const int klimit = min(q0 + 128, kend);
    const int nt = (klimit + 63) >> 6;

    auto loadTile = [&](int tile) {
        const uint32_t base = sb + (uint32_t)(tile & 1) * ASTG;
        const size_t go = bofs + (size_t)(tile * 64) * Dn;
        const __nv_bfloat16* srcs[4] = { g_kh + go, g_kl + go, g_vh + go, g_vl + go };
        #pragma unroll
        for (int i = 0; i < 8; ++i) {
            const int arr = i >> 1;
            const int c2 = t + (i & 1) * 256;     // 0..511
            const int kr = c2 >> 3, q = c2 & 7;
            cpa16(base + (uint32_t)arr * 9216 + (uint32_t)kr * 144 + (uint32_t)q * 16,
                  srcs[arr] + (size_t)kr * Dn + q * 8);
        }
        CP_COMMIT();
    };

    loadTile(0);

    for (int tile = 0; tile < nt; ++tile) {
        const int j0 = tile * 64;
        CP_WAIT(0);
        __syncthreads();
        if (tile + 1 < nt) loadTile(tile + 1);

        const uint32_t stoff = (uint32_t)(tile & 1) * ASTG;

        // --- S = Q K^T (bf16x3) via ldmatrix ---
        float sc[8][4];
        #pragma unroll
        for (int n = 0; n < 8; ++n) {
            float c[4] = {0.f, 0.f, 0.f, 0.f};
            const uint32_t ka = kbase + stoff + (uint32_t)n * 1152;
            #pragma unroll
            for (int ks = 0; ks < 4; ++ks) {
                uint32_t b0h, b1h, b0l, b1l;
                LDSM_X4(b0h, b1h, b0l, b1l, ka + (uint32_t)ks * 32);
                MMA16816(c, qhf[ks][0], qhf[ks][1], qhf[ks][2], qhf[ks][3], b0h, b1h);
                MMA16816(c, qhf[ks][0], qhf[ks][1], qhf[ks][2], qhf[ks][3], b0l, b1l);
                MMA16816(c, qlf[ks][0], qlf[ks][1], qlf[ks][2], qlf[ks][3], b0h, b1h);
            }
            sc[n][0] = c[0]; sc[n][1] = c[1]; sc[n][2] = c[2]; sc[n][3] = c[3];
        }

        // --- mask + register online softmax ---
        float mx0 = -1e30f, mx1 = -1e30f;
        #pragma unroll
        for (int n = 0; n < 8; ++n) {
            int col = j0 + n * 8 + 2 * tig;
            sc[n][0] = (col     <= row0 && col     < kend) ? sc[n][0] : -1e30f;
            sc[n][1] = (col + 1 <= row0 && col + 1 < kend) ? sc[n][1] : -1e30f;
            sc[n][2] = (col     <= row1 && col     < kend) ? sc[n][2] : -1e30f;
            sc[n][3] = (col + 1 <= row1 && col + 1 < kend) ? sc[n][3] : -1e30f;
            mx0 = fmaxf(mx0, fmaxf(sc[n][0], sc[n][1]));
            mx1 = fmaxf(mx1, fmaxf(sc[n][2], sc[n][3]));
        }
        mx0 = fmaxf(mx0, __shfl_xor_sync(0xffffffffu, mx0, 1));
        mx0 = fmaxf(mx0, __shfl_xor_sync(0xffffffffu, mx0, 2));
        mx1 = fmaxf(mx1, __shfl_xor_sync(0xffffffffu, mx1, 1));
        mx1 = fmaxf(mx1, __shfl_xor_sync(0xffffffffu, mx1, 2));

        float nm0 = fmaxf(m0r, mx0), nm1 = fmaxf(m1r, mx1);
        float al0 = __expf(m0r - nm0), al1 = __expf(m1r - nm1);
        m0r = nm0; m1r = nm1;

        float s0 = 0.f, s1 = 0.f;
        #pragma unroll
        for (int n = 0; n < 8; ++n) {
            sc[n][0] = __expf(sc[n][0] - nm0);
            sc[n][1] = __expf(sc[n][1] - nm0);
            sc[n][2] = __expf(sc[n][2] - nm1);
            sc[n][3] = __expf(sc[n][3] - nm1);
            s0 += sc[n][0] + sc[n][1];
            s1 += sc[n][2] + sc[n][3];
        }
        s0 += __shfl_xor_sync(0xffffffffu, s0, 1);
        s0 += __shfl_xor_sync(0xffffffffu, s0, 2);
        s1 += __shfl_xor_sync(0xffffffffu, s1, 1);
        s1 += __shfl_xor_sync(0xffffffffu, s1, 2);
        l0r = l0r * al0 + s0;
        l1r = l1r * al1 + s1;

        #pragma unroll
        for (int n = 0; n < 8; ++n) {
            oc[n][0] *= al0; oc[n][1] *= al0;
            oc[n][2] *= al1; oc[n][3] *= al1;
        }

        // --- O += P V (bf16x3), V via ldmatrix.trans ---
        #pragma unroll
        for (int ks = 0; ks < 4; ++ks) {
            float r0, r1;
            uint32_t a0h, a1h, a2h, a3h, a0l, a1l, a2l, a3l;
            a0h = pack_hi(sc[2*ks][0],   sc[2*ks][1],   r0, r1); a0l = pack_bf(r0, r1);
            a1h = pack_hi(sc[2*ks][2],   sc[2*ks][3],   r0, r1); a1l = pack_bf(r0, r1);
            a2h = pack_hi(sc[2*ks+1][0], sc[2*ks+1][1], r0, r1); a2l = pack_bf(r0, r1);
            a3h = pack_hi(sc[2*ks+1][2], sc[2*ks+1][3], r0, r1); a3l = pack_bf(r0, r1);
            const uint32_t va = vbase + stoff + (uint32_t)ks * 2304;
            #pragma unroll
            for (int n = 0; n < 8; ++n) {
                uint32_t b0h, b1h, b0l, b1l;
                LDSM_X4_T(b0h, b1h, b0l, b1l, va + (uint32_t)n * 16);
                MMA16816(oc[n], a0h, a1h, a2h, a3h, b0h, b1h);
                MMA16816(oc[n], a0h, a1h, a2h, a3h, b0l, b1l);
                MMA16816(oc[n], a0l, a1l, a2l, a3l, b0h, b1h);
            }
        }
    }

    // --- epilogue: normalize + tf32-round + store ---
    float invA = 1.f / l0r;
    float invB = 1.f / l1r;
    float* Ob = Outp + bofs + (size_t)row0 * Dn;
    #pragma unroll
    for (int n = 0; n < 8; ++n) {
        int cc = n * 8 + 2 * tig;
        *(float2*)&Ob[cc] =
            make_float2(tf32r(oc[n][0] * invA), tf32r(oc[n][1] * invA));
        *(float2*)(Ob + 8 * (size_t)Dn + cc) =
            make_float2(tf32r(oc[n][2] * invB), tf32r(oc[n][3] * invB));
    }
}

// ---------------------------------------------------------------------------
extern "C" void kernel_launch(void* const* d_in, const int* in_sizes, int n_in,
                              void* d_out, int out_size)
{
    const float* x   = (const float*)d_in[0];
    const int*   eff = (const int*)d_in[1];
    const float* Wq  = (const float*)d_in[2];
    const float* bq  = (const float*)d_in[3];
    const float* Wk  = (const float*)d_in[4];
    const float* bk  = (const float*)d_in[5];
    const float* Wv  = (const float*)d_in[6];
    const float* bv  = (const float*)d_in[7];
    const float* Wo  = (const float*)d_in[8];
    const float* bo  = (const float*)d_in[9];
    float* out = (float*)d_out;

    float *att, *xr, *wqr, *wkr, *wvr, *wor;
    cudaGetSymbolAddress((void**)&att, g_att);
    cudaGetSymbolAddress((void**)&xr,  g_xr);
    cudaGetSymbolAddress((void**)&wqr, g_wqr);
    cudaGetSymbolAddress((void**)&wkr, g_wkr);
    cudaGetSymbolAddress((void**)&wvr, g_wvr);
    cudaGetSymbolAddress((void**)&wor, g_wor);

    cudaFuncSetAttribute(gemm_mma<0>,
                         cudaFuncAttributeMaxDynamicSharedMemorySize, GSMEM);
    cudaFuncSetAttribute(gemm_mma<1>,
                         cudaFuncAttributeMaxDynamicSharedMemorySize, GSMEM);
    cudaFuncSetAttribute(attn4,
                         cudaFuncAttributeMaxDynamicSharedMemorySize, ATT_SMEM);

    rope_table_kernel<<<(Sn * 32) / 256, 256>>>();
    round_kernel<<<(Mn * Dn + 4 * Dn * Dn) / 1024, 256>>>(x, Wq, Wk, Wv, Wo);

    // fused QKV projection (24 n-tiles x 32 m-tiles)
    gemm_mma<1><<<dim3(24, 32), 256, GSMEM>>>(xr, wqr, wkr, wvr,
                                              bq, bk, bv, nullptr);

    attn4<<<dim3(Sn / 128, Hn, Bn), 256, ATT_SMEM>>>(eff, att);

    // O projection
    gemm_mma<0><<<dim3(8, 32), 256, GSMEM>>>(att, wor, nullptr, nullptr,
                                             bo, nullptr, nullptr, out);
}

// round 8
// speedup vs baseline: 3.3084x; 1.0568x over previous
#include <cuda_runtime.h>
#include <cuda_bf16.h>
#include <cstdint>

#define Bn 2
#define Sn 2048
#define Dn 1024
#define Hn 16
#define HDn 64
#define Mn (Bn*Sn)

// Scratch (allocation-free rule: device globals)
__device__ float g_att[Mn*Dn];
__device__ float g_xr[Mn*Dn];                 // tf32-rounded x
__device__ float g_wqr[Dn*Dn], g_wkr[Dn*Dn], g_wvr[Dn*Dn], g_wor[Dn*Dn];
__device__ float g_cos[Sn*32];
__device__ float g_sin[Sn*32];
__device__ __nv_bfloat16 g_qh[Mn*Dn], g_ql[Mn*Dn];
__device__ __nv_bfloat16 g_kh[Mn*Dn], g_kl[Mn*Dn];
__device__ __nv_bfloat16 g_vh[Mn*Dn], g_vl[Mn*Dn];

// ---------------------------------------------------------------------------
__device__ __forceinline__ void cpa16(uint32_t dst, const void* src) {
    asm volatile("cp.async.cg.shared.global [%0], [%1], 16;" :: "r"(dst), "l"(src));
}
#define CP_COMMIT() asm volatile("cp.async.commit_group;" ::: "memory")
#define CP_WAIT(n)  asm volatile("cp.async.wait_group %0;" :: "n"(n) : "memory")

__device__ __forceinline__ uint32_t smem_u32(const void* p) {
    uint32_t a;
    asm("{ .reg .u64 t; cvta.to.shared.u64 t, %1; cvt.u32.u64 %0, t; }"
        : "=r"(a) : "l"(p));
    return a;
}

__device__ __forceinline__ float tf32r(float x) {
    float y;
    asm("cvt.rna.tf32.f32 %0, %1;" : "=f"(y) : "f"(x));
    return y;
}

// mma m16n8k8 tf32 -> f32
#define MMA_TF32(c, a0, a1, a2, a3, b0, b1)                                   \
    asm volatile(                                                             \
        "mma.sync.aligned.m16n8k8.row.col.f32.tf32.tf32.f32 "                 \
        "{%0,%1,%2,%3},{%4,%5,%6,%7},{%8,%9},{%0,%1,%2,%3};"                  \
        : "+f"((c)[0]), "+f"((c)[1]), "+f"((c)[2]), "+f"((c)[3])              \
        : "r"(a0), "r"(a1), "r"(a2), "r"(a3), "r"(b0), "r"(b1))

// mma m16n8k16 bf16 -> f32
#define MMA16816(c, a0, a1, a2, a3, b0, b1)                                   \
    asm volatile(                                                             \
        "mma.sync.aligned.m16n8k16.row.col.f32.bf16.bf16.f32 "                \
        "{%0,%1,%2,%3}, {%4,%5,%6,%7}, {%8,%9}, {%0,%1,%2,%3};"               \
        : "+f"((c)[0]), "+f"((c)[1]), "+f"((c)[2]), "+f"((c)[3])              \
        : "r"(a0), "r"(a1), "r"(a2), "r"(a3), "r"(b0), "r"(b1))

#define LDSM_X4(d0,d1,d2,d3,a)                                                \
    asm volatile("ldmatrix.sync.aligned.m8n8.x4.shared.b16 {%0,%1,%2,%3}, [%4];" \
        : "=r"(d0), "=r"(d1), "=r"(d2), "=r"(d3) : "r"(a))
#define LDSM_X4_T(d0,d1,d2,d3,a)                                              \
    asm volatile("ldmatrix.sync.aligned.m8n8.x4.trans.shared.b16 {%0,%1,%2,%3}, [%4];" \
        : "=r"(d0), "=r"(d1), "=r"(d2), "=r"(d3) : "r"(a))

__device__ __forceinline__ uint32_t pack_hi(float a, float b,
                                            float& ra, float& rb) {
    __nv_bfloat16 h0 = __float2bfloat16(a);
    __nv_bfloat16 h1 = __float2bfloat16(b);
    ra = a - __bfloat162float(h0);
    rb = b - __bfloat162float(h1);
    __nv_bfloat162 hh; hh.x = h0; hh.y = h1;
    return *(uint32_t*)&hh;
}
__device__ __forceinline__ uint32_t pack_bf(float a, float b) {
    __nv_bfloat162 hh;
    hh.x = __float2bfloat16(a);
    hh.y = __float2bfloat16(b);
    return *(uint32_t*)&hh;
}

// ---------------------------------------------------------------------------
// RoPE tables
// ---------------------------------------------------------------------------
__global__ void rope_table_kernel() {
    int idx = blockIdx.x * 256 + threadIdx.x;
    int pos = idx >> 5;
    int i   = idx & 31;
    float inv = exp2f(-(float)i * 0.4152410118609203f);  // log2(10000)/32
    float ang = (float)pos * inv;
    float s, c;
    sincosf(ang, &s, &c);
    g_cos[idx] = c;
    g_sin[idx] = s;
}

// ---------------------------------------------------------------------------
// tf32 pre-rounding of x and the four weight matrices
// ---------------------------------------------------------------------------
__global__ void round_kernel(const float* __restrict__ x,
                             const float* __restrict__ wq,
                             const float* __restrict__ wk,
                             const float* __restrict__ wv,
                             const float* __restrict__ wo)
{
    int i4 = (blockIdx.x * 256 + threadIdx.x) * 4;
    const float* src;
    float* dst;
    int off;
    if (i4 < Mn * Dn) {
        src = x; dst = g_xr; off = i4;
    } else {
        int j = i4 - Mn * Dn;
        int w = j >> 20;
        off = j & ((1 << 20) - 1);
        src = (w == 0) ? wq : (w == 1) ? wk : (w == 2) ? wv : wo;
        dst = (w == 0) ? g_wqr : (w == 1) ? g_wkr : (w == 2) ? g_wvr : g_wor;
    }
    float4 v = *(const float4*)(src + off);
    v.x = tf32r(v.x); v.y = tf32r(v.y); v.z = tf32r(v.z); v.w = tf32r(v.w);
    *(float4*)(dst + off) = v;
}

// ---------------------------------------------------------------------------
// Raw-mma tf32 GEMM with ldmatrix fragment loads.
// 128x128 tile, BK=32, 2-stage cp.async, row stride 144 B (conflict-free).
// 8 warps (4m x 2n), warp tile 32x64, register epilogue.
// tf32-via-b16 ldmatrix: an 8x4 fp32 block viewed as 8x8 b16 delivers
// fp32 (r,c) to lane 4r+c — exactly the m16n8k8 tf32 fragment layout.
// ---------------------------------------------------------------------------
#define LDT3 36
#define TILE3 (128 * LDT3)
#define STG3  (2 * TILE3)
#define GSMEM (2 * STG3 * 4)        // 73728 bytes

// Q scale with log2(e) folded in (softmax done in base 2)
#define QSCALE 0.18033688011112043f

template<int MODE>
__global__ void __launch_bounds__(256, 2) gemm_mma(
    const float* __restrict__ A,
    const float* __restrict__ W0, const float* __restrict__ W1,
    const float* __restrict__ W2,
    const float* __restrict__ b0p, const float* __restrict__ b1p,
    const float* __restrict__ b2p,
    float* __restrict__ C)
{
    extern __shared__ float smem[];
    const uint32_t sb = smem_u32(smem);
    const int tid = threadIdx.x;
    const int wid = tid >> 5, lane = tid & 31;
    const int g = lane >> 2, tig = lane & 3;
    const int wm = wid & 3, wn = wid >> 2;
    const int m0 = blockIdx.y * 128;

    int wsel = 0, n0;
    const float* W;
    const float* bias;
    if (MODE == 1) {
        wsel = blockIdx.x >> 3;
        n0 = (blockIdx.x & 7) * 128;
        W    = (wsel == 0) ? W0 : (wsel == 1) ? W1 : W2;
        bias = (wsel == 0) ? b0p : (wsel == 1) ? b1p : b2p;
    } else {
        n0 = blockIdx.x * 128;
        W = W0; bias = b0p;
    }

    // per-lane ldmatrix addresses (stage-relative bytes)
    const int l8 = lane & 7;
    const int lh = (lane >> 3) & 1;     // matrix pair selector
    const int lq = (lane >> 4) & 1;
    // A quadrants: m0/m1 = row halves @ col 0, m2/m3 = row halves @ col +4
    uint32_t aoff[2];
    #pragma unroll
    for (int mi = 0; mi < 2; ++mi)
        aoff[mi] = (uint32_t)((wm * 32 + mi * 16 + lh * 8 + l8) * 144 + lq * 16);
    // B pairs: m0/m1 = nj k-lo/k-hi, m2/m3 = nj+1 k-lo/k-hi
    uint32_t boff[4];
    #pragma unroll
    for (int j = 0; j < 4; ++j)
        boff[j] = (uint32_t)(TILE3 * 4 +
                  (wn * 64 + (2 * j + lq) * 8 + l8) * 144 + lh * 16);

    auto loadChunk = [&](int c) {
        const int s = c & 1;
        const uint32_t abase = sb + s * STG3 * 4;
        const uint32_t wbase = abase + TILE3 * 4;
        const float* Ab = A + (size_t)m0 * Dn + c * 32;
        const float* Wb = W + (size_t)n0 * Dn + c * 32;
        #pragma unroll
        for (int i = 0; i < 4; ++i) {
            int task = tid + i * 256;
            int row = task >> 3;
            int q   = task & 7;
            uint32_t off = (uint32_t)(row * 144 + q * 16);
            cpa16(abase + off, Ab + (size_t)row * Dn + q * 4);
            cpa16(wbase + off, Wb + (size_t)row * Dn + q * 4);
        }
    };

    float acc[2][8][4];
    #pragma unroll
    for (int mi = 0; mi < 2; ++mi)
        #pragma unroll
        for (int nj = 0; nj < 8; ++nj)
            #pragma unroll
            for (int e = 0; e < 4; ++e) acc[mi][nj][e] = 0.0f;

    loadChunk(0); CP_COMMIT();

    for (int c = 0; c < 32; ++c) {
        if (c + 1 < 32) { loadChunk(c + 1); CP_COMMIT(); CP_WAIT(1); }
        else            { CP_WAIT(0); }
        __syncthreads();

        const uint32_t stb = sb + (uint32_t)(c & 1) * (STG3 * 4);

        #pragma unroll
        for (int k8 = 0; k8 < 4; ++k8) {
            const uint32_t kb = (uint32_t)k8 * 32;
            uint32_t a[2][4];
            LDSM_X4(a[0][0], a[0][1], a[0][2], a[0][3], stb + aoff[0] + kb);
            LDSM_X4(a[1][0], a[1][1], a[1][2], a[1][3], stb + aoff[1] + kb);
            #pragma unroll
            for (int j = 0; j < 4; ++j) {
                uint32_t b00, b01, b10, b11;
                LDSM_X4(b00, b01, b10, b11, stb + boff[j] + kb);
                MMA_TF32(acc[0][2*j],   a[0][0], a[0][1], a[0][2], a[0][3], b00, b01);
                MMA_TF32(acc[1][2*j],   a[1][0], a[1][1], a[1][2], a[1][3], b00, b01);
                MMA_TF32(acc[0][2*j+1], a[0][0], a[0][1], a[0][2], a[0][3], b10, b11);
                MMA_TF32(acc[1][2*j+1], a[1][0], a[1][1], a[1][2], a[1][3], b10, b11);
            }
        }
        __syncthreads();
    }

    #pragma unroll
    for (int mi = 0; mi < 2; ++mi) {
        #pragma unroll
        for (int nj = 0; nj < 8; ++nj) {
            const int col_l = wn * 64 + nj * 8 + 2 * tig;
            #pragma unroll
            for (int e2 = 0; e2 < 2; ++e2) {
                const int row = m0 + wm * 32 + mi * 16 + g + e2 * 8;
                float v0 = acc[mi][nj][e2 * 2 + 0] + __ldg(&bias[col_l]);
                float v1 = acc[mi][nj][e2 * 2 + 1] + __ldg(&bias[col_l + 1]);
                if (MODE == 0) {
                    *(float2*)(C + (size_t)row * Dn + n0 + col_l) =
                        make_float2(v0, v1);
                } else {
                    if (wsel < 2) {
                        const int pos = row & (Sn - 1);
                        const int i0 = (col_l & 63) >> 1;
                        float cc = g_cos[pos * 32 + i0];
                        float ss = g_sin[pos * 32 + i0];
                        float o0 = v0 * cc - v1 * ss;
                        float o1 = v0 * ss + v1 * cc;
                        v0 = o0; v1 = o1;
                    }
                    if (wsel == 0) { v0 *= QSCALE; v1 *= QSCALE; }
                    float r0, r1;
                    uint32_t hh = pack_hi(v0, v1, r0, r1);
                    uint32_t ll = pack_bf(r0, r1);
                    const size_t idx = (size_t)row * Dn + n0 + col_l;
                    __nv_bfloat16* dh = (wsel == 0) ? g_qh : (wsel == 1) ? g_kh : g_vh;
                    __nv_bfloat16* dl = (wsel == 0) ? g_ql : (wsel == 1) ? g_kl : g_vl;
                    *(uint32_t*)(dh + idx) = hh;
                    *(uint32_t*)(dl + idx) = ll;
                }
            }
        }
    }
}

// ---------------------------------------------------------------------------
// Flash attention v4: ldmatrix fragments + cp.async double-buffered tiles.
// Softmax in base-2 (log2e folded into Q scale at projection time).
// ---------------------------------------------------------------------------
#define ASTG 36864
#define ATT_SMEM (2 * ASTG)

__global__ void __launch_bounds__(256, 2) attn4(const int* __restrict__ eff,
                                                float* __restrict__ Outp)
{
    extern __shared__ char sm[];
    const uint32_t sb = smem_u32(sm);

    const int t = threadIdx.x, w = t >> 5, lane = t & 31;
    const int g = lane >> 2, tig = lane & 3;
    const int part = lane >> 3, r8 = lane & 7;
    const int q0 = ((int)gridDim.x - 1 - (int)blockIdx.x) * 128;
    const int h = blockIdx.y, b = blockIdx.z;
    const int kend = Sn - eff[b];
    const size_t bofs = (size_t)b * Sn * Dn + h * HDn;

    const int row0 = q0 + w * 16 + g;
    const int row1 = row0 + 8;

    const uint32_t kbase = sb + (part < 2 ? 0u : 9216u)
                         + (uint32_t)r8 * 144 + (uint32_t)(part & 1) * 16;
    const uint32_t vbase = sb + 18432u + (part < 2 ? 0u : 9216u)
                         + (uint32_t)(part & 1) * 1152 + (uint32_t)r8 * 144;

    // --- Q fragments (hi/lo) in registers ---
    uint32_t qhf[4][4], qlf[4][4];
    {
        const __nv_bfloat16* bh = g_qh + bofs + (size_t)row0 * Dn;
        const __nv_bfloat16* bl = g_ql + bofs + (size_t)row0 * Dn;
        #pragma unroll
        for (int ks = 0; ks < 4; ++ks) {
            int d0 = ks * 16 + 2 * tig;
            qhf[ks][0] = *(const uint32_t*)(bh + d0);
            qhf[ks][1] = *(const uint32_t*)(bh + 8 * (size_t)Dn + d0);
            qhf[ks][2] = *(const uint32_t*)(bh + d0 + 8);
            qhf[ks][3] = *(const uint32_t*)(bh + 8 * (size_t)Dn + d0 + 8);
            qlf[ks][0] = *(const uint32_t*)(bl + d0);
            qlf[ks][1] = *(const uint32_t*)(bl + 8 * (size_t)Dn + d0);
            qlf[ks][2] = *(const uint32_t*)(bl + d0 + 8);
            qlf[ks][3] = *(const uint32_t*)(bl + 8 * (size_t)Dn + d0 + 8);
        }
    }

    float oc[8][4];
    #pragma unroll
    for (int n = 0; n < 8; ++n) { oc[n][0]=0.f; oc[n][1]=0.f; oc[n][2]=0.f; oc[n][3]=0.f; }
    float m0r = -1e30f, m1r = -1e30f, l0r = 0.f, l1r = 0.f;

    const int klimit = min(q0 + 128, kend);
    const int nt = (klimit + 63) >> 6;

    auto loadTile = [&](int tile) {
        const uint32_t base = sb + (uint32_t)(tile & 1) * ASTG;
        const size_t go = bofs + (size_t)(tile * 64) * Dn;
        const __nv_bfloat16* srcs[4] = { g_kh + go, g_kl + go, g_vh + go, g_vl + go };
        #pragma unroll
        for (int i = 0; i < 8; ++i) {
            const int arr = i >> 1;
            const int c2 = t + (i & 1) * 256;     // 0..511
            const int kr = c2 >> 3, q = c2 & 7;
            cpa16(base + (uint32_t)arr * 9216 + (uint32_t)kr * 144 + (uint32_t)q * 16,
                  srcs[arr] + (size_t)kr * Dn + q * 8);
        }
        CP_COMMIT();
    };

    loadTile(0);

    for (int tile = 0; tile < nt; ++tile) {
        const int j0 = tile * 64;
        CP_WAIT(0);
        __syncthreads();
        if (tile + 1 < nt) loadTile(tile + 1);

        const uint32_t stoff = (uint32_t)(tile & 1) * ASTG;

        // --- S = Q K^T (bf16x3) via ldmatrix ---
        float sc[8][4];
        #pragma unroll
        for (int n = 0; n < 8; ++n) {
            float c[4] = {0.f, 0.f, 0.f, 0.f};
            const uint32_t ka = kbase + stoff + (uint32_t)n * 1152;
            #pragma unroll
            for (int ks = 0; ks < 4; ++ks) {
                uint32_t b0h, b1h, b0l, b1l;
                LDSM_X4(b0h, b1h, b0l, b1l, ka + (uint32_t)ks * 32);
                MMA16816(c, qhf[ks][0], qhf[ks][1], qhf[ks][2], qhf[ks][3], b0h, b1h);
                MMA16816(c, qhf[ks][0], qhf[ks][1], qhf[ks][2], qhf[ks][3], b0l, b1l);
                MMA16816(c, qlf[ks][0], qlf[ks][1], qlf[ks][2], qlf[ks][3], b0h, b1h);
            }
            sc[n][0] = c[0]; sc[n][1] = c[1]; sc[n][2] = c[2]; sc[n][3] = c[3];
        }

        // --- mask + register online softmax (base-2) ---
        float mx0 = -1e30f, mx1 = -1e30f;
        #pragma unroll
        for (int n = 0; n < 8; ++n) {
            int col = j0 + n * 8 + 2 * tig;
            sc[n][0] = (col     <= row0 && col     < kend) ? sc[n][0] : -1e30f;
            sc[n][1] = (col + 1 <= row0 && col + 1 < kend) ? sc[n][1] : -1e30f;
            sc[n][2] = (col     <= row1 && col     < kend) ? sc[n][2] : -1e30f;
            sc[n][3] = (col + 1 <= row1 && col + 1 < kend) ? sc[n][3] : -1e30f;
            mx0 = fmaxf(mx0, fmaxf(sc[n][0], sc[n][1]));
            mx1 = fmaxf(mx1, fmaxf(sc[n][2], sc[n][3]));
        }
        mx0 = fmaxf(mx0, __shfl_xor_sync(0xffffffffu, mx0, 1));
        mx0 = fmaxf(mx0, __shfl_xor_sync(0xffffffffu, mx0, 2));
        mx1 = fmaxf(mx1, __shfl_xor_sync(0xffffffffu, mx1, 1));
        mx1 = fmaxf(mx1, __shfl_xor_sync(0xffffffffu, mx1, 2));

        float nm0 = fmaxf(m0r, mx0), nm1 = fmaxf(m1r, mx1);
        float al0 = exp2f(m0r - nm0), al1 = exp2f(m1r - nm1);
        m0r = nm0; m1r = nm1;

        float s0 = 0.f, s1 = 0.f;
        #pragma unroll
        for (int n = 0; n < 8; ++n) {
            sc[n][0] = exp2f(sc[n][0] - nm0);
            sc[n][1] = exp2f(sc[n][1] - nm0);
            sc[n][2] = exp2f(sc[n][2] - nm1);
            sc[n][3] = exp2f(sc[n][3] - nm1);
            s0 += sc[n][0] + sc[n][1];
            s1 += sc[n][2] + sc[n][3];
        }
        s0 += __shfl_xor_sync(0xffffffffu, s0, 1);
        s0 += __shfl_xor_sync(0xffffffffu, s0, 2);
        s1 += __shfl_xor_sync(0xffffffffu, s1, 1);
        s1 += __shfl_xor_sync(0xffffffffu, s1, 2);
        l0r = l0r * al0 + s0;
        l1r = l1r * al1 + s1;

        #pragma unroll
        for (int n = 0; n < 8; ++n) {
            oc[n][0] *= al0; oc[n][1] *= al0;
            oc[n][2] *= al1; oc[n][3] *= al1;
        }

        // --- O += P V (bf16x3), V via ldmatrix.trans ---
        #pragma unroll
        for (int ks = 0; ks < 4; ++ks) {
            float r0, r1;
            uint32_t a0h, a1h, a2h, a3h, a0l, a1l, a2l, a3l;
            a0h = pack_hi(sc[2*ks][0],   sc[2*ks][1],   r0, r1); a0l = pack_bf(r0, r1);
            a1h = pack_hi(sc[2*ks][2],   sc[2*ks][3],   r0, r1); a1l = pack_bf(r0, r1);
            a2h = pack_hi(sc[2*ks+1][0], sc[2*ks+1][1], r0, r1); a2l = pack_bf(r0, r1);
            a3h = pack_hi(sc[2*ks+1][2], sc[2*ks+1][3], r0, r1); a3l = pack_bf(r0, r1);
            const uint32_t va = vbase + stoff + (uint32_t)ks * 2304;
            #pragma unroll
            for (int n = 0; n < 8; ++n) {
                uint32_t b0h, b1h, b0l, b1l;
                LDSM_X4_T(b0h, b1h, b0l, b1l, va + (uint32_t)n * 16);
                MMA16816(oc[n], a0h, a1h, a2h, a3h, b0h, b1h);
                MMA16816(oc[n], a0h, a1h, a2h, a3h, b0l, b1l);
                MMA16816(oc[n], a0l, a1l, a2l, a3l, b0h, b1h);
            }
        }
    }

    // --- epilogue: normalize + tf32-round + store ---
    float invA = 1.f / l0r;
    float invB = 1.f / l1r;
    float* Ob = Outp + bofs + (size_t)row0 * Dn;
    #pragma unroll
    for (int n = 0; n < 8; ++n) {
        int cc = n * 8 + 2 * tig;
        *(float2*)&Ob[cc] =
            make_float2(tf32r(oc[n][0] * invA), tf32r(oc[n][1] * invA));
        *(float2*)(Ob + 8 * (size_t)Dn + cc) =
            make_float2(tf32r(oc[n][2] * invB), tf32r(oc[n][3] * invB));
    }
}

// ---------------------------------------------------------------------------
extern "C" void kernel_launch(void* const* d_in, const int* in_sizes, int n_in,
                              void* d_out, int out_size)
{
    const float* x   = (const float*)d_in[0];
    const int*   eff = (const int*)d_in[1];
    const float* Wq  = (const float*)d_in[2];
    const float* bq  = (const float*)d_in[3];
    const float* Wk  = (const float*)d_in[4];
    const float* bk  = (const float*)d_in[5];
    const float* Wv  = (const float*)d_in[6];
    const float* bv  = (const float*)d_in[7];
    const float* Wo  = (const float*)d_in[8];
    const float* bo  = (const float*)d_in[9];
    float* out = (float*)d_out;

    float *att, *xr, *wqr, *wkr, *wvr, *wor;
    cudaGetSymbolAddress((void**)&att, g_att);
    cudaGetSymbolAddress((void**)&xr,  g_xr);
    cudaGetSymbolAddress((void**)&wqr, g_wqr);
    cudaGetSymbolAddress((void**)&wkr, g_wkr);
    cudaGetSymbolAddress((void**)&wvr, g_wvr);
    cudaGetSymbolAddress((void**)&wor, g_wor);

    cudaFuncSetAttribute(gemm_mma<0>,
                         cudaFuncAttributeMaxDynamicSharedMemorySize, GSMEM);
    cudaFuncSetAttribute(gemm_mma<1>,
                         cudaFuncAttributeMaxDynamicSharedMemorySize, GSMEM);
    cudaFuncSetAttribute(attn4,
                         cudaFuncAttributeMaxDynamicSharedMemorySize, ATT_SMEM);

    rope_table_kernel<<<(Sn * 32) / 256, 256>>>();
    round_kernel<<<(Mn * Dn + 4 * Dn * Dn) / 1024, 256>>>(x, Wq, Wk, Wv, Wo);

    // fused QKV projection (24 n-tiles x 32 m-tiles)
    gemm_mma<1><<<dim3(24, 32), 256, GSMEM>>>(xr, wqr, wkr, wvr,
                                              bq, bk, bv, nullptr);

    attn4<<<dim3(Sn / 128, Hn, Bn), 256, ATT_SMEM>>>(eff, att);

    // O projection
    gemm_mma<0><<<dim3(8, 32), 256, GSMEM>>>(att, wor, nullptr, nullptr,
                                             bo, nullptr, nullptr, out);
}

// round 10
// speedup vs baseline: 3.4434x; 1.0408x over previous
#include <cuda_runtime.h>
#include <cuda_bf16.h>
#include <cstdint>

#define Bn 2
#define Sn 2048
#define Dn 1024
#define Hn 16
#define HDn 64
#define Mn (Bn*Sn)

// Scratch (allocation-free rule: device globals)
__device__ float g_att[Mn*Dn];
__device__ float g_xr[Mn*Dn];                 // tf32-rounded x
__device__ float g_wqr[Dn*Dn], g_wkr[Dn*Dn], g_wvr[Dn*Dn], g_wor[Dn*Dn];
__device__ float g_cos[Sn*32];
__device__ float g_sin[Sn*32];
__device__ __nv_bfloat16 g_qh[Mn*Dn], g_ql[Mn*Dn];
__device__ __nv_bfloat16 g_kh[Mn*Dn], g_kl[Mn*Dn];
__device__ __nv_bfloat16 g_vh[Mn*Dn], g_vl[Mn*Dn];

// ---------------------------------------------------------------------------
__device__ __forceinline__ void cpa16(uint32_t dst, const void* src) {
    asm volatile("cp.async.cg.shared.global [%0], [%1], 16;" :: "r"(dst), "l"(src));
}
#define CP_COMMIT() asm volatile("cp.async.commit_group;" ::: "memory")
#define CP_WAIT(n)  asm volatile("cp.async.wait_group %0;" :: "n"(n) : "memory")

__device__ __forceinline__ uint32_t smem_u32(const void* p) {
    uint32_t a;
    asm("{ .reg .u64 t; cvta.to.shared.u64 t, %1; cvt.u32.u64 %0, t; }"
        : "=r"(a) : "l"(p));
    return a;
}

__device__ __forceinline__ float tf32r(float x) {
    float y;
    asm("cvt.rna.tf32.f32 %0, %1;" : "=f"(y) : "f"(x));
    return y;
}

// single-MUFU exp2
__device__ __forceinline__ float ex2(float x) {
    float y;
    asm("ex2.approx.f32 %0, %1;" : "=f"(y) : "f"(x));
    return y;
}

// exact-residual bf16 hi/lo split of a float pair, 6 instructions.
// hh = {bf16(a) lo, bf16(b) hi}; ll = residuals likewise.
__device__ __forceinline__ void split2(float a, float b,
                                       uint32_t& hh, uint32_t& ll) {
    asm("cvt.rn.bf16x2.f32 %0, %1, %2;" : "=r"(hh) : "f"(b), "f"(a));
    float ha = __uint_as_float(hh << 16);
    float hb = __uint_as_float(hh & 0xFFFF0000u);
    float la = a - ha;
    float lb = b - hb;
    asm("cvt.rn.bf16x2.f32 %0, %1, %2;" : "=r"(ll) : "f"(lb), "f"(la));
}

// mma m16n8k8 tf32 -> f32
#define MMA_TF32(c, a0, a1, a2, a3, b0, b1)                                   \
    asm volatile(                                                             \
        "mma.sync.aligned.m16n8k8.row.col.f32.tf32.tf32.f32 "                 \
        "{%0,%1,%2,%3},{%4,%5,%6,%7},{%8,%9},{%0,%1,%2,%3};"                  \
        : "+f"((c)[0]), "+f"((c)[1]), "+f"((c)[2]), "+f"((c)[3])              \
        : "r"(a0), "r"(a1), "r"(a2), "r"(a3), "r"(b0), "r"(b1))

// mma m16n8k16 bf16 -> f32
#define MMA16816(c, a0, a1, a2, a3, b0, b1)                                   \
    asm volatile(                                                             \
        "mma.sync.aligned.m16n8k16.row.col.f32.bf16.bf16.f32 "                \
        "{%0,%1,%2,%3}, {%4,%5,%6,%7}, {%8,%9}, {%0,%1,%2,%3};"               \
        : "+f"((c)[0]), "+f"((c)[1]), "+f"((c)[2]), "+f"((c)[3])              \
        : "r"(a0), "r"(a1), "r"(a2), "r"(a3), "r"(b0), "r"(b1))

#define LDSM_X4(d0,d1,d2,d3,a)                                                \
    asm volatile("ldmatrix.sync.aligned.m8n8.x4.shared.b16 {%0,%1,%2,%3}, [%4];" \
        : "=r"(d0), "=r"(d1), "=r"(d2), "=r"(d3) : "r"(a))
#define LDSM_X4_T(d0,d1,d2,d3,a)                                              \
    asm volatile("ldmatrix.sync.aligned.m8n8.x4.trans.shared.b16 {%0,%1,%2,%3}, [%4];" \
        : "=r"(d0), "=r"(d1), "=r"(d2), "=r"(d3) : "r"(a))

// ---------------------------------------------------------------------------
// RoPE tables
// ---------------------------------------------------------------------------
__global__ void rope_table_kernel() {
    int idx = blockIdx.x * 256 + threadIdx.x;
    int pos = idx >> 5;
    int i   = idx & 31;
    float inv = exp2f(-(float)i * 0.4152410118609203f);  // log2(10000)/32
    float ang = (float)pos * inv;
    float s, c;
    sincosf(ang, &s, &c);
    g_cos[idx] = c;
    g_sin[idx] = s;
}

// ---------------------------------------------------------------------------
// tf32 pre-rounding of x and the four weight matrices
// ---------------------------------------------------------------------------
__global__ void round_kernel(const float* __restrict__ x,
                             const float* __restrict__ wq,
                             const float* __restrict__ wk,
                             const float* __restrict__ wv,
                             const float* __restrict__ wo)
{
    int i4 = (blockIdx.x * 256 + threadIdx.x) * 4;
    const float* src;
    float* dst;
    int off;
    if (i4 < Mn * Dn) {
        src = x; dst = g_xr; off = i4;
    } else {
        int j = i4 - Mn * Dn;
        int w = j >> 20;
        off = j & ((1 << 20) - 1);
        src = (w == 0) ? wq : (w == 1) ? wk : (w == 2) ? wv : wo;
        dst = (w == 0) ? g_wqr : (w == 1) ? g_wkr : (w == 2) ? g_wvr : g_wor;
    }
    float4 v = *(const float4*)(src + off);
    v.x = tf32r(v.x); v.y = tf32r(v.y); v.z = tf32r(v.z); v.w = tf32r(v.w);
    *(float4*)(dst + off) = v;
}

// ---------------------------------------------------------------------------
// Raw-mma tf32 GEMM with ldmatrix fragment loads (structure unchanged).
// ---------------------------------------------------------------------------
#define LDT3 36
#define TILE3 (128 * LDT3)
#define STG3  (2 * TILE3)
#define GSMEM (2 * STG3 * 4)        // 73728 bytes

// Q scale with log2(e) folded in (softmax done in base 2)
#define QSCALE 0.18033688011112043f

template<int MODE>
__global__ void __launch_bounds__(256, 2) gemm_mma(
    const float* __restrict__ A,
    const float* __restrict__ W0, const float* __restrict__ W1,
    const float* __restrict__ W2,
    const float* __restrict__ b0p, const float* __restrict__ b1p,
    const float* __restrict__ b2p,
    float* __restrict__ C)
{
    extern __shared__ float smem[];
    const uint32_t sb = smem_u32(smem);
    const int tid = threadIdx.x;
    const int wid = tid >> 5, lane = tid & 31;
    const int g = lane >> 2, tig = lane & 3;
    const int wm = wid & 3, wn = wid >> 2;
    const int m0 = blockIdx.y * 128;

    int wsel = 0, n0;
    const float* W;
    const float* bias;
    if (MODE == 1) {
        wsel = blockIdx.x >> 3;
        n0 = (blockIdx.x & 7) * 128;
        W    = (wsel == 0) ? W0 : (wsel == 1) ? W1 : W2;
        bias = (wsel == 0) ? b0p : (wsel == 1) ? b1p : b2p;
    } else {
        n0 = blockIdx.x * 128;
        W = W0; bias = b0p;
    }

    const int l8 = lane & 7;
    const int lh = (lane >> 3) & 1;
    const int lq = (lane >> 4) & 1;
    uint32_t aoff[2];
    #pragma unroll
    for (int mi = 0; mi < 2; ++mi)
        aoff[mi] = (uint32_t)((wm * 32 + mi * 16 + lh * 8 + l8) * 144 + lq * 16);
    uint32_t boff[4];
    #pragma unroll
    for (int j = 0; j < 4; ++j)
        boff[j] = (uint32_t)(TILE3 * 4 +
                  (wn * 64 + (2 * j + lq) * 8 + l8) * 144 + lh * 16);

    auto loadChunk = [&](int c) {
        const int s = c & 1;
        const uint32_t abase = sb + s * STG3 * 4;
        const uint32_t wbase = abase + TILE3 * 4;
        const float* Ab = A + (size_t)m0 * Dn + c * 32;
        const float* Wb = W + (size_t)n0 * Dn + c * 32;
        #pragma unroll
        for (int i = 0; i < 4; ++i) {
            int task = tid + i * 256;
            int row = task >> 3;
            int q   = task & 7;
            uint32_t off = (uint32_t)(row * 144 + q * 16);
            cpa16(abase + off, Ab + (size_t)row * Dn + q * 4);
            cpa16(wbase + off, Wb + (size_t)row * Dn + q * 4);
        }
    };

    float acc[2][8][4];
    #pragma unroll
    for (int mi = 0; mi < 2; ++mi)
        #pragma unroll
        for (int nj = 0; nj < 8; ++nj)
            #pragma unroll
            for (int e = 0; e < 4; ++e) acc[mi][nj][e] = 0.0f;

    loadChunk(0); CP_COMMIT();

    for (int c = 0; c < 32; ++c) {
        if (c + 1 < 32) { loadChunk(c + 1); CP_COMMIT(); CP_WAIT(1); }
        else            { CP_WAIT(0); }
        __syncthreads();

        const uint32_t stb = sb + (uint32_t)(c & 1) * (STG3 * 4);

        #pragma unroll
        for (int k8 = 0; k8 < 4; ++k8) {
            const uint32_t kb = (uint32_t)k8 * 32;
            uint32_t a[2][4];
            LDSM_X4(a[0][0], a[0][1], a[0][2], a[0][3], stb + aoff[0] + kb);
            LDSM_X4(a[1][0], a[1][1], a[1][2], a[1][3], stb + aoff[1] + kb);
            #pragma unroll
            for (int j = 0; j < 4; ++j) {
                uint32_t b00, b01, b10, b11;
                LDSM_X4(b00, b01, b10, b11, stb + boff[j] + kb);
                MMA_TF32(acc[0][2*j],   a[0][0], a[0][1], a[0][2], a[0][3], b00, b01);
                MMA_TF32(acc[1][2*j],   a[1][0], a[1][1], a[1][2], a[1][3], b00, b01);
                MMA_TF32(acc[0][2*j+1], a[0][0], a[0][1], a[0][2], a[0][3], b10, b11);
                MMA_TF32(acc[1][2*j+1], a[1][0], a[1][1], a[1][2], a[1][3], b10, b11);
            }
        }
        __syncthreads();
    }

    #pragma unroll
    for (int mi = 0; mi < 2; ++mi) {
        #pragma unroll
        for (int nj = 0; nj < 8; ++nj) {
            const int col_l = wn * 64 + nj * 8 + 2 * tig;
            #pragma unroll
            for (int e2 = 0; e2 < 2; ++e2) {
                const int row = m0 + wm * 32 + mi * 16 + g + e2 * 8;
                float v0 = acc[mi][nj][e2 * 2 + 0] + __ldg(&bias[col_l]);
                float v1 = acc[mi][nj][e2 * 2 + 1] + __ldg(&bias[col_l + 1]);
                if (MODE == 0) {
                    *(float2*)(C + (size_t)row * Dn + n0 + col_l) =
                        make_float2(v0, v1);
                } else {
                    if (wsel < 2) {
                        const int pos = row & (Sn - 1);
                        const int i0 = (col_l & 63) >> 1;
                        float cc = g_cos[pos * 32 + i0];
                        float ss = g_sin[pos * 32 + i0];
                        float o0 = v0 * cc - v1 * ss;
                        float o1 = v0 * ss + v1 * cc;
                        v0 = o0; v1 = o1;
                    }
                    if (wsel == 0) { v0 *= QSCALE; v1 *= QSCALE; }
                    uint32_t hh, ll;
                    split2(v0, v1, hh, ll);
                    const size_t idx = (size_t)row * Dn + n0 + col_l;
                    __nv_bfloat16* dh = (wsel == 0) ? g_qh : (wsel == 1) ? g_kh : g_vh;
                    __nv_bfloat16* dl = (wsel == 0) ? g_ql : (wsel == 1) ? g_kl : g_vl;
                    *(uint32_t*)(dh + idx) = hh;
                    *(uint32_t*)(dl + idx) = ll;
                }
            }
        }
    }
}

// ---------------------------------------------------------------------------
// Flash attention v5: ldmatrix + double buffer + interior fast path +
// single-MUFU exp2 + cheap hi/lo splits.
// ---------------------------------------------------------------------------
#define ASTG 36864
#define ATT_SMEM (2 * ASTG)

__global__ void __launch_bounds__(256, 2) attn5(const int* __restrict__ eff,
                                                float* __restrict__ Outp)
{
    extern __shared__ char sm[];
    const uint32_t sb = smem_u32(sm);

    const int t = threadIdx.x, w = t >> 5, lane = t & 31;
    const int g = lane >> 2, tig = lane & 3;
    const int part = lane >> 3, r8 = lane & 7;
    const int q0 = ((int)gridDim.x - 1 - (int)blockIdx.x) * 128;
    const int h = blockIdx.y, b = blockIdx.z;
    const int kend = Sn - eff[b];
    const size_t bofs = (size_t)b * Sn * Dn + h * HDn;

    const int row0 = q0 + w * 16 + g;
    const int row1 = row0 + 8;

    const uint32_t kbase = sb + (part < 2 ? 0u : 9216u)
                         + (uint32_t)r8 * 144 + (uint32_t)(part & 1) * 16;
    const uint32_t vbase = sb + 18432u + (part < 2 ? 0u : 9216u)
                         + (uint32_t)(part & 1) * 1152 + (uint32_t)r8 * 144;

    // --- Q fragments (hi/lo) in registers ---
    uint32_t qhf[4][4], qlf[4][4];
    {
        const __nv_bfloat16* bh = g_qh + bofs + (size_t)row0 * Dn;
        const __nv_bfloat16* bl = g_ql + bofs + (size_t)row0 * Dn;
        #pragma unroll
        for (int ks = 0; ks < 4; ++ks) {
            int d0 = ks * 16 + 2 * tig;
            qhf[ks][0] = *(const uint32_t*)(bh + d0);
            qhf[ks][1] = *(const uint32_t*)(bh + 8 * (size_t)Dn + d0);
            qhf[ks][2] = *(const uint32_t*)(bh + d0 + 8);
            qhf[ks][3] = *(const uint32_t*)(bh + 8 * (size_t)Dn + d0 + 8);
            qlf[ks][0] = *(const uint32_t*)(bl + d0);
            qlf[ks][1] = *(const uint32_t*)(bl + 8 * (size_t)Dn + d0);
            qlf[ks][2] = *(const uint32_t*)(bl + d0 + 8);
            qlf[ks][3] = *(const uint32_t*)(bl + 8 * (size_t)Dn + d0 + 8);
        }
    }

    float oc[8][4];
    #pragma unroll
    for (int n = 0; n < 8; ++n) { oc[n][0]=0.f; oc[n][1]=0.f; oc[n][2]=0.f; oc[n][3]=0.f; }
    float m0r = -1e30f, m1r = -1e30f, l0r = 0.f, l1r = 0.f;

    const int klimit = min(q0 + 128, kend);
    const int nt = (klimit + 63) >> 6;

    auto loadTile = [&](int tile) {
        const uint32_t base = sb + (uint32_t)(tile & 1) * ASTG;
        const size_t go = bofs + (size_t)(tile * 64) * Dn;
        const __nv_bfloat16* srcs[4] = { g_kh + go, g_kl + go, g_vh + go, g_vl + go };
        #pragma unroll
        for (int i = 0; i < 8; ++i) {
            const int arr = i >> 1;
            const int c2 = t + (i & 1) * 256;     // 0..511
            const int kr = c2 >> 3, q = c2 & 7;
            cpa16(base + (uint32_t)arr * 9216 + (uint32_t)kr * 144 + (uint32_t)q * 16,
                  srcs[arr] + (size_t)kr * Dn + q * 8);
        }
        CP_COMMIT();
    };

    loadTile(0);

    for (int tile = 0; tile < nt; ++tile) {
        const int j0 = tile * 64;
        CP_WAIT(0);
        __syncthreads();
        if (tile + 1 < nt) loadTile(tile + 1);

        const uint32_t stoff = (uint32_t)(tile & 1) * ASTG;

        // --- S = Q K^T (bf16x3) via ldmatrix ---
        float sc[8][4];
        #pragma unroll
        for (int n = 0; n < 8; ++n) {
            float c[4] = {0.f, 0.f, 0.f, 0.f};
            const uint32_t ka = kbase + stoff + (uint32_t)n * 1152;
            #pragma unroll
            for (int ks = 0; ks < 4; ++ks) {
                uint32_t b0h, b1h, b0l, b1l;
                LDSM_X4(b0h, b1h, b0l, b1l, ka + (uint32_t)ks * 32);
                MMA16816(c, qhf[ks][0], qhf[ks][1], qhf[ks][2], qhf[ks][3], b0h, b1h);
                MMA16816(c, qhf[ks][0], qhf[ks][1], qhf[ks][2], qhf[ks][3], b0l, b1l);
                MMA16816(c, qlf[ks][0], qlf[ks][1], qlf[ks][2], qlf[ks][3], b0h, b1h);
            }
            sc[n][0] = c[0]; sc[n][1] = c[1]; sc[n][2] = c[2]; sc[n][3] = c[3];
        }

        // --- mask (skipped for interior tiles; warp-uniform test) ---
        const bool interior = (j0 + 63 <= q0 + w * 16) && (j0 + 64 <= kend);
        if (!interior) {
            #pragma unroll
            for (int n = 0; n < 8; ++n) {
                int col = j0 + n * 8 + 2 * tig;
                sc[n][0] = (col     <= row0 && col     < kend) ? sc[n][0] : -1e30f;
                sc[n][1] = (col + 1 <= row0 && col + 1 < kend) ? sc[n][1] : -1e30f;
                sc[n][2] = (col     <= row1 && col     < kend) ? sc[n][2] : -1e30f;
                sc[n][3] = (col + 1 <= row1 && col + 1 < kend) ? sc[n][3] : -1e30f;
            }
        }

        // --- register online softmax (base-2, single-MUFU exp) ---
        float mx0 = -1e30f, mx1 = -1e30f;
        #pragma unroll
        for (int n = 0; n < 8; ++n) {
            mx0 = fmaxf(mx0, fmaxf(sc[n][0], sc[n][1]));
            mx1 = fmaxf(mx1, fmaxf(sc[n][2], sc[n][3]));
        }
        mx0 = fmaxf(mx0, __shfl_xor_sync(0xffffffffu, mx0, 1));
        mx0 = fmaxf(mx0, __shfl_xor_sync(0xffffffffu, mx0, 2));
        mx1 = fmaxf(mx1, __shfl_xor_sync(0xffffffffu, mx1, 1));
        mx1 = fmaxf(mx1, __shfl_xor_sync(0xffffffffu, mx1, 2));

        float nm0 = fmaxf(m0r, mx0), nm1 = fmaxf(m1r, mx1);
        float al0 = ex2(m0r - nm0), al1 = ex2(m1r - nm1);
        m0r = nm0; m1r = nm1;

        float s0 = 0.f, s1 = 0.f;
        #pragma unroll
        for (int n = 0; n < 8; ++n) {
            sc[n][0] = ex2(sc[n][0] - nm0);
            sc[n][1] = ex2(sc[n][1] - nm0);
            sc[n][2] = ex2(sc[n][2] - nm1);
            sc[n][3] = ex2(sc[n][3] - nm1);
            s0 += sc[n][0] + sc[n][1];
            s1 += sc[n][2] + sc[n][3];
        }
        s0 += __shfl_xor_sync(0xffffffffu, s0, 1);
        s0 += __shfl_xor_sync(0xffffffffu, s0, 2);
        s1 += __shfl_xor_sync(0xffffffffu, s1, 1);
        s1 += __shfl_xor_sync(0xffffffffu, s1, 2);
        l0r = l0r * al0 + s0;
        l1r = l1r * al1 + s1;

        #pragma unroll
        for (int n = 0; n < 8; ++n) {
            oc[n][0] *= al0; oc[n][1] *= al0;
            oc[n][2] *= al1; oc[n][3] *= al1;
        }

        // --- O += P V (bf16x3), V via ldmatrix.trans ---
        #pragma unroll
        for (int ks = 0; ks < 4; ++ks) {
            uint32_t a0h, a1h, a2h, a3h, a0l, a1l, a2l, a3l;
            split2(sc[2*ks][0],   sc[2*ks][1],   a0h, a0l);
            split2(sc[2*ks][2],   sc[2*ks][3],   a1h, a1l);
            split2(sc[2*ks+1][0], sc[2*ks+1][1], a2h, a2l);
            split2(sc[2*ks+1][2], sc[2*ks+1][3], a3h, a3l);
            const uint32_t va = vbase + stoff + (uint32_t)ks * 2304;
            #pragma unroll
            for (int n = 0; n < 8; ++n) {
                uint32_t b0h, b1h, b0l, b1l;
                LDSM_X4_T(b0h, b1h, b0l, b1l, va + (uint32_t)n * 16);
                MMA16816(oc[n], a0h, a1h, a2h, a3h, b0h, b1h);
                MMA16816(oc[n], a0h, a1h, a2h, a3h, b0l, b1l);
                MMA16816(oc[n], a0l, a1l, a2l, a3l, b0h, b1h);
            }
        }
    }

    // --- epilogue: normalize + tf32-round + store ---
    float invA = 1.f / l0r;
    float invB = 1.f / l1r;
    float* Ob = Outp + bofs + (size_t)row0 * Dn;
    #pragma unroll
    for (int n = 0; n < 8; ++n) {
        int cc = n * 8 + 2 * tig;
        *(float2*)&Ob[cc] =
            make_float2(tf32r(oc[n][0] * invA), tf32r(oc[n][1] * invA));
        *(float2*)(Ob + 8 * (size_t)Dn + cc) =
            make_float2(tf32r(oc[n][2] * invB), tf32r(oc[n][3] * invB));
    }
}

// ---------------------------------------------------------------------------
extern "C" void kernel_launch(void* const* d_in, const int* in_sizes, int n_in,
                              void* d_out, int out_size)
{
    const float* x   = (const float*)d_in[0];
    const int*   eff = (const int*)d_in[1];
    const float* Wq  = (const float*)d_in[2];
    const float* bq  = (const float*)d_in[3];
    const float* Wk  = (const float*)d_in[4];
    const float* bk  = (const float*)d_in[5];
    const float* Wv  = (const float*)d_in[6];
    const float* bv  = (const float*)d_in[7];
    const float* Wo  = (const float*)d_in[8];
    const float* bo  = (const float*)d_in[9];
    float* out = (float*)d_out;

    float *att, *xr, *wqr, *wkr, *wvr, *wor;
    cudaGetSymbolAddress((void**)&att, g_att);
    cudaGetSymbolAddress((void**)&xr,  g_xr);
    cudaGetSymbolAddress((void**)&wqr, g_wqr);
    cudaGetSymbolAddress((void**)&wkr, g_wkr);
    cudaGetSymbolAddress((void**)&wvr, g_wvr);
    cudaGetSymbolAddress((void**)&wor, g_wor);

    cudaFuncSetAttribute(gemm_mma<0>,
                         cudaFuncAttributeMaxDynamicSharedMemorySize, GSMEM);
    cudaFuncSetAttribute(gemm_mma<1>,
                         cudaFuncAttributeMaxDynamicSharedMemorySize, GSMEM);
    cudaFuncSetAttribute(attn5,
                         cudaFuncAttributeMaxDynamicSharedMemorySize, ATT_SMEM);

    rope_table_kernel<<<(Sn * 32) / 256, 256>>>();
    round_kernel<<<(Mn * Dn + 4 * Dn * Dn) / 1024, 256>>>(x, Wq, Wk, Wv, Wo);

    // fused QKV projection (24 n-tiles x 32 m-tiles)
    gemm_mma<1><<<dim3(24, 32), 256, GSMEM>>>(xr, wqr, wkr, wvr,
                                              bq, bk, bv, nullptr);

    attn5<<<dim3(Sn / 128, Hn, Bn), 256, ATT_SMEM>>>(eff, att);

    // O projection
    gemm_mma<0><<<dim3(8, 32), 256, GSMEM>>>(att, wor, nullptr, nullptr,
                                             bo, nullptr, nullptr, out);
}

// round 11
// speedup vs baseline: 3.5579x; 1.0333x over previous
#include <cuda_runtime.h>
#include <cuda_bf16.h>
#include <cstdint>

#define Bn 2
#define Sn 2048
#define Dn 1024
#define Hn 16
#define HDn 64
#define Mn (Bn*Sn)

// Scratch (allocation-free rule: device globals)
__device__ float g_att[Mn*Dn];
__device__ float g_xr[Mn*Dn];                 // tf32-rounded x
__device__ float g_wqr[Dn*Dn], g_wkr[Dn*Dn], g_wvr[Dn*Dn], g_wor[Dn*Dn];
__device__ float g_cos[Sn*32];
__device__ float g_sin[Sn*32];
__device__ __nv_bfloat16 g_qh[Mn*Dn], g_ql[Mn*Dn];
__device__ __nv_bfloat16 g_kh[Mn*Dn], g_kl[Mn*Dn];
__device__ __nv_bfloat16 g_vh[Mn*Dn], g_vl[Mn*Dn];

// ---------------------------------------------------------------------------
__device__ __forceinline__ void cpa16(uint32_t dst, const void* src) {
    asm volatile("cp.async.cg.shared.global [%0], [%1], 16;" :: "r"(dst), "l"(src));
}
#define CP_COMMIT() asm volatile("cp.async.commit_group;" ::: "memory")
#define CP_WAIT(n)  asm volatile("cp.async.wait_group %0;" :: "n"(n) : "memory")

__device__ __forceinline__ uint32_t smem_u32(const void* p) {
    uint32_t a;
    asm("{ .reg .u64 t; cvta.to.shared.u64 t, %1; cvt.u32.u64 %0, t; }"
        : "=r"(a) : "l"(p));
    return a;
}

__device__ __forceinline__ float tf32r(float x) {
    float y;
    asm("cvt.rna.tf32.f32 %0, %1;" : "=f"(y) : "f"(x));
    return y;
}

// single-MUFU exp2
__device__ __forceinline__ float ex2(float x) {
    float y;
    asm("ex2.approx.f32 %0, %1;" : "=f"(y) : "f"(x));
    return y;
}

// exact-residual bf16 hi/lo split of a float pair, 6 instructions.
__device__ __forceinline__ void split2(float a, float b,
                                       uint32_t& hh, uint32_t& ll) {
    asm("cvt.rn.bf16x2.f32 %0, %1, %2;" : "=r"(hh) : "f"(b), "f"(a));
    float ha = __uint_as_float(hh << 16);
    float hb = __uint_as_float(hh & 0xFFFF0000u);
    float la = a - ha;
    float lb = b - hb;
    asm("cvt.rn.bf16x2.f32 %0, %1, %2;" : "=r"(ll) : "f"(lb), "f"(la));
}

// mma m16n8k8 tf32 -> f32
#define MMA_TF32(c, a0, a1, a2, a3, b0, b1)                                   \
    asm volatile(                                                             \
        "mma.sync.aligned.m16n8k8.row.col.f32.tf32.tf32.f32 "                 \
        "{%0,%1,%2,%3},{%4,%5,%6,%7},{%8,%9},{%0,%1,%2,%3};"                  \
        : "+f"((c)[0]), "+f"((c)[1]), "+f"((c)[2]), "+f"((c)[3])              \
        : "r"(a0), "r"(a1), "r"(a2), "r"(a3), "r"(b0), "r"(b1))

// mma m16n8k16 bf16 -> f32
#define MMA16816(c, a0, a1, a2, a3, b0, b1)                                   \
    asm volatile(                                                             \
        "mma.sync.aligned.m16n8k16.row.col.f32.bf16.bf16.f32 "                \
        "{%0,%1,%2,%3}, {%4,%5,%6,%7}, {%8,%9}, {%0,%1,%2,%3};"               \
        : "+f"((c)[0]), "+f"((c)[1]), "+f"((c)[2]), "+f"((c)[3])              \
        : "r"(a0), "r"(a1), "r"(a2), "r"(a3), "r"(b0), "r"(b1))

#define LDSM_X4(d0,d1,d2,d3,a)                                                \
    asm volatile("ldmatrix.sync.aligned.m8n8.x4.shared.b16 {%0,%1,%2,%3}, [%4];" \
        : "=r"(d0), "=r"(d1), "=r"(d2), "=r"(d3) : "r"(a))
#define LDSM_X4_T(d0,d1,d2,d3,a)                                              \
    asm volatile("ldmatrix.sync.aligned.m8n8.x4.trans.shared.b16 {%0,%1,%2,%3}, [%4];" \
        : "=r"(d0), "=r"(d1), "=r"(d2), "=r"(d3) : "r"(a))

#define ONESBF 0x3F803F80u

// ---------------------------------------------------------------------------
// Fused prep: RoPE tables + tf32 pre-rounding of x and the four W matrices.
// ---------------------------------------------------------------------------
__global__ void prep_kernel(const float* __restrict__ x,
                            const float* __restrict__ wq,
                            const float* __restrict__ wk,
                            const float* __restrict__ wv,
                            const float* __restrict__ wo)
{
    int gidx = blockIdx.x * 256 + threadIdx.x;

    if (gidx < Sn * 32) {        // RoPE tables (first 256 blocks)
        int pos = gidx >> 5;
        int i   = gidx & 31;
        float inv = exp2f(-(float)i * 0.4152410118609203f);  // log2(10000)/32
        float ang = (float)pos * inv;
        float s, c;
        sincosf(ang, &s, &c);
        g_cos[gidx] = c;
        g_sin[gidx] = s;
    }

    int i4 = gidx * 4;
    const float* src;
    float* dst;
    int off;
    if (i4 < Mn * Dn) {
        src = x; dst = g_xr; off = i4;
    } else {
        int j = i4 - Mn * Dn;
        int w = j >> 20;
        off = j & ((1 << 20) - 1);
        src = (w == 0) ? wq : (w == 1) ? wk : (w == 2) ? wv : wo;
        dst = (w == 0) ? g_wqr : (w == 1) ? g_wkr : (w == 2) ? g_wvr : g_wor;
    }
    float4 v = *(const float4*)(src + off);
    v.x = tf32r(v.x); v.y = tf32r(v.y); v.z = tf32r(v.z); v.w = tf32r(v.w);
    *(float4*)(dst + off) = v;
}

// ---------------------------------------------------------------------------
// Raw-mma tf32 GEMM, ldmatrix fragments, 3-stage cp.async, 1 barrier/chunk.
// ---------------------------------------------------------------------------
#define LDT3 36
#define TILE3 (128 * LDT3)
#define STG3  (2 * TILE3)
#define GSMEM (3 * STG3 * 4)        // 110592 bytes

// Q scale with log2(e) folded in (softmax done in base 2)
#define QSCALE 0.18033688011112043f

template<int MODE>
__global__ void __launch_bounds__(256, 2) gemm_mma(
    const float* __restrict__ A,
    const float* __restrict__ W0, const float* __restrict__ W1,
    const float* __restrict__ W2,
    const float* __restrict__ b0p, const float* __restrict__ b1p,
    const float* __restrict__ b2p,
    float* __restrict__ C)
{
    extern __shared__ float smem[];
    const uint32_t sb = smem_u32(smem);
    const int tid = threadIdx.x;
    const int wid = tid >> 5, lane = tid & 31;
    const int g = lane >> 2, tig = lane & 3;
    const int wm = wid & 3, wn = wid >> 2;
    const int m0 = blockIdx.y * 128;

    int wsel = 0, n0;
    const float* W;
    const float* bias;
    if (MODE == 1) {
        wsel = blockIdx.x >> 3;
        n0 = (blockIdx.x & 7) * 128;
        W    = (wsel == 0) ? W0 : (wsel == 1) ? W1 : W2;
        bias = (wsel == 0) ? b0p : (wsel == 1) ? b1p : b2p;
    } else {
        n0 = blockIdx.x * 128;
        W = W0; bias = b0p;
    }

    const int l8 = lane & 7;
    const int lh = (lane >> 3) & 1;
    const int lq = (lane >> 4) & 1;
    uint32_t aoff[2];
    #pragma unroll
    for (int mi = 0; mi < 2; ++mi)
        aoff[mi] = (uint32_t)((wm * 32 + mi * 16 + lh * 8 + l8) * 144 + lq * 16);
    uint32_t boff[4];
    #pragma unroll
    for (int j = 0; j < 4; ++j)
        boff[j] = (uint32_t)(TILE3 * 4 +
                  (wn * 64 + (2 * j + lq) * 8 + l8) * 144 + lh * 16);

    auto loadChunk = [&](int c) {
        const uint32_t abase = sb + (uint32_t)(c % 3) * (STG3 * 4);
        const uint32_t wbase = abase + TILE3 * 4;
        const float* Ab = A + (size_t)m0 * Dn + c * 32;
        const float* Wb = W + (size_t)n0 * Dn + c * 32;
        #pragma unroll
        for (int i = 0; i < 4; ++i) {
            int task = tid + i * 256;
            int row = task >> 3;
            int q   = task & 7;
            uint32_t off = (uint32_t)(row * 144 + q * 16);
            cpa16(abase + off, Ab + (size_t)row * Dn + q * 4);
            cpa16(wbase + off, Wb + (size_t)row * Dn + q * 4);
        }
        CP_COMMIT();
    };

    float acc[2][8][4];
    #pragma unroll
    for (int mi = 0; mi < 2; ++mi)
        #pragma unroll
        for (int nj = 0; nj < 8; ++nj)
            #pragma unroll
            for (int e = 0; e < 4; ++e) acc[mi][nj][e] = 0.0f;

    loadChunk(0); loadChunk(1);

    for (int c = 0; c < 32; ++c) {
        if (c + 1 < 32) CP_WAIT(1);
        else            CP_WAIT(0);
        __syncthreads();
        if (c + 2 < 32) loadChunk(c + 2);

        const uint32_t stb = sb + (uint32_t)(c % 3) * (STG3 * 4);

        #pragma unroll
        for (int k8 = 0; k8 < 4; ++k8) {
            const uint32_t kb = (uint32_t)k8 * 32;
            uint32_t a[2][4];
            LDSM_X4(a[0][0], a[0][1], a[0][2], a[0][3], stb + aoff[0] + kb);
            LDSM_X4(a[1][0], a[1][1], a[1][2], a[1][3], stb + aoff[1] + kb);
            #pragma unroll
            for (int j = 0; j < 4; ++j) {
                uint32_t b00, b01, b10, b11;
                LDSM_X4(b00, b01, b10, b11, stb + boff[j] + kb);
                MMA_TF32(acc[0][2*j],   a[0][0], a[0][1], a[0][2], a[0][3], b00, b01);
                MMA_TF32(acc[1][2*j],   a[1][0], a[1][1], a[1][2], a[1][3], b00, b01);
                MMA_TF32(acc[0][2*j+1], a[0][0], a[0][1], a[0][2], a[0][3], b10, b11);
                MMA_TF32(acc[1][2*j+1], a[1][0], a[1][1], a[1][2], a[1][3], b10, b11);
            }
        }
    }

    #pragma unroll
    for (int mi = 0; mi < 2; ++mi) {
        #pragma unroll
        for (int nj = 0; nj < 8; ++nj) {
            const int col_l = wn * 64 + nj * 8 + 2 * tig;
            #pragma unroll
            for (int e2 = 0; e2 < 2; ++e2) {
                const int row = m0 + wm * 32 + mi * 16 + g + e2 * 8;
                float v0 = acc[mi][nj][e2 * 2 + 0] + __ldg(&bias[col_l]);
                float v1 = acc[mi][nj][e2 * 2 + 1] + __ldg(&bias[col_l + 1]);
                if (MODE == 0) {
                    *(float2*)(C + (size_t)row * Dn + n0 + col_l) =
                        make_float2(v0, v1);
                } else {
                    if (wsel < 2) {
                        const int pos = row & (Sn - 1);
                        const int i0 = (col_l & 63) >> 1;
                        float cc = g_cos[pos * 32 + i0];
                        float ss = g_sin[pos * 32 + i0];
                        float o0 = v0 * cc - v1 * ss;
                        float o1 = v0 * ss + v1 * cc;
                        v0 = o0; v1 = o1;
                    }
                    if (wsel == 0) { v0 *= QSCALE; v1 *= QSCALE; }
                    uint32_t hh, ll;
                    split2(v0, v1, hh, ll);
                    const size_t idx = (size_t)row * Dn + n0 + col_l;
                    __nv_bfloat16* dh = (wsel == 0) ? g_qh : (wsel == 1) ? g_kh : g_vh;
                    __nv_bfloat16* dl = (wsel == 0) ? g_ql : (wsel == 1) ? g_kl : g_vl;
                    *(uint32_t*)(dh + idx) = hh;
                    *(uint32_t*)(dl + idx) = ll;
                }
            }
        }
    }
}

// ---------------------------------------------------------------------------
// Flash attention v6: 3-stage pipeline + mma row-sum (ones column).
// ---------------------------------------------------------------------------
#define ASTG 36864
#define ATT_SMEM (3 * ASTG)         // 110592

__global__ void __launch_bounds__(256, 2) attn6(const int* __restrict__ eff,
                                                float* __restrict__ Outp)
{
    extern __shared__ char sm[];
    const uint32_t sb = smem_u32(sm);

    const int t = threadIdx.x, w = t >> 5, lane = t & 31;
    const int g = lane >> 2, tig = lane & 3;
    const int part = lane >> 3, r8 = lane & 7;
    const int q0 = ((int)gridDim.x - 1 - (int)blockIdx.x) * 128;
    const int h = blockIdx.y, b = blockIdx.z;
    const int kend = Sn - eff[b];
    const size_t bofs = (size_t)b * Sn * Dn + h * HDn;

    const int row0 = q0 + w * 16 + g;
    const int row1 = row0 + 8;

    const uint32_t kbase = sb + (part < 2 ? 0u : 9216u)
                         + (uint32_t)r8 * 144 + (uint32_t)(part & 1) * 16;
    const uint32_t vbase = sb + 18432u + (part < 2 ? 0u : 9216u)
                         + (uint32_t)(part & 1) * 1152 + (uint32_t)r8 * 144;

    // --- Q fragments (hi/lo) in registers ---
    uint32_t qhf[4][4], qlf[4][4];
    {
        const __nv_bfloat16* bh = g_qh + bofs + (size_t)row0 * Dn;
        const __nv_bfloat16* bl = g_ql + bofs + (size_t)row0 * Dn;
        #pragma unroll
        for (int ks = 0; ks < 4; ++ks) {
            int d0 = ks * 16 + 2 * tig;
            qhf[ks][0] = *(const uint32_t*)(bh + d0);
            qhf[ks][1] = *(const uint32_t*)(bh + 8 * (size_t)Dn + d0);
            qhf[ks][2] = *(const uint32_t*)(bh + d0 + 8);
            qhf[ks][3] = *(const uint32_t*)(bh + 8 * (size_t)Dn + d0 + 8);
            qlf[ks][0] = *(const uint32_t*)(bl + d0);
            qlf[ks][1] = *(const uint32_t*)(bl + 8 * (size_t)Dn + d0);
            qlf[ks][2] = *(const uint32_t*)(bl + d0 + 8);
            qlf[ks][3] = *(const uint32_t*)(bl + 8 * (size_t)Dn + d0 + 8);
        }
    }

    float oc[8][4];
    #pragma unroll
    for (int n = 0; n < 8; ++n) { oc[n][0]=0.f; oc[n][1]=0.f; oc[n][2]=0.f; oc[n][3]=0.f; }
    float m0r = -1e30f, m1r = -1e30f, l0r = 0.f, l1r = 0.f;

    const int klimit = min(q0 + 128, kend);
    const int nt = (klimit + 63) >> 6;

    auto loadTile = [&](int tile) {
        const uint32_t base = sb + (uint32_t)(tile % 3) * ASTG;
        const size_t go = bofs + (size_t)(tile * 64) * Dn;
        const __nv_bfloat16* srcs[4] = { g_kh + go, g_kl + go, g_vh + go, g_vl + go };
        #pragma unroll
        for (int i = 0; i < 8; ++i) {
            const int arr = i >> 1;
            const int c2 = t + (i & 1) * 256;     // 0..511
            const int kr = c2 >> 3, q = c2 & 7;
            cpa16(base + (uint32_t)arr * 9216 + (uint32_t)kr * 144 + (uint32_t)q * 16,
                  srcs[arr] + (size_t)kr * Dn + q * 8);
        }
        CP_COMMIT();
    };

    loadTile(0);
    if (nt > 1) loadTile(1);

    for (int tile = 0; tile < nt; ++tile) {
        const int j0 = tile * 64;
        if (tile + 1 < nt) CP_WAIT(1);
        else               CP_WAIT(0);
        __syncthreads();
        if (tile + 2 < nt) loadTile(tile + 2);

        const uint32_t stoff = (uint32_t)(tile % 3) * ASTG;

        // --- S = Q K^T (bf16x3) via ldmatrix ---
        float sc[8][4];
        #pragma unroll
        for (int n = 0; n < 8; ++n) {
            float c[4] = {0.f, 0.f, 0.f, 0.f};
            const uint32_t ka = kbase + stoff + (uint32_t)n * 1152;
            #pragma unroll
            for (int ks = 0; ks < 4; ++ks) {
                uint32_t b0h, b1h, b0l, b1l;
                LDSM_X4(b0h, b1h, b0l, b1l, ka + (uint32_t)ks * 32);
                MMA16816(c, qhf[ks][0], qhf[ks][1], qhf[ks][2], qhf[ks][3], b0h, b1h);
                MMA16816(c, qhf[ks][0], qhf[ks][1], qhf[ks][2], qhf[ks][3], b0l, b1l);
                MMA16816(c, qlf[ks][0], qlf[ks][1], qlf[ks][2], qlf[ks][3], b0h, b1h);
            }
            sc[n][0] = c[0]; sc[n][1] = c[1]; sc[n][2] = c[2]; sc[n][3] = c[3];
        }

        // --- mask (skipped for interior tiles; warp-uniform test) ---
        const bool interior = (j0 + 63 <= q0 + w * 16) && (j0 + 64 <= kend);
        if (!interior) {
            #pragma unroll
            for (int n = 0; n < 8; ++n) {
                int col = j0 + n * 8 + 2 * tig;
                sc[n][0] = (col     <= row0 && col     < kend) ? sc[n][0] : -1e30f;
                sc[n][1] = (col + 1 <= row0 && col + 1 < kend) ? sc[n][1] : -1e30f;
                sc[n][2] = (col     <= row1 && col     < kend) ? sc[n][2] : -1e30f;
                sc[n][3] = (col + 1 <= row1 && col + 1 < kend) ? sc[n][3] : -1e30f;
            }
        }

        // --- register online softmax (base-2); row max via shfl ---
        float mx0 = -1e30f, mx1 = -1e30f;
        #pragma unroll
        for (int n = 0; n < 8; ++n) {
            mx0 = fmaxf(mx0, fmaxf(sc[n][0], sc[n][1]));
            mx1 = fmaxf(mx1, fmaxf(sc[n][2], sc[n][3]));
        }
        mx0 = fmaxf(mx0, __shfl_xor_sync(0xffffffffu, mx0, 1));
        mx0 = fmaxf(mx0, __shfl_xor_sync(0xffffffffu, mx0, 2));
        mx1 = fmaxf(mx1, __shfl_xor_sync(0xffffffffu, mx1, 1));
        mx1 = fmaxf(mx1, __shfl_xor_sync(0xffffffffu, mx1, 2));

        float nm0 = fmaxf(m0r, mx0), nm1 = fmaxf(m1r, mx1);
        float al0 = ex2(m0r - nm0), al1 = ex2(m1r - nm1);
        m0r = nm0; m1r = nm1;

        #pragma unroll
        for (int n = 0; n < 8; ++n) {
            sc[n][0] = ex2(sc[n][0] - nm0);
            sc[n][1] = ex2(sc[n][1] - nm0);
            sc[n][2] = ex2(sc[n][2] - nm1);
            sc[n][3] = ex2(sc[n][3] - nm1);
        }

        #pragma unroll
        for (int n = 0; n < 8; ++n) {
            oc[n][0] *= al0; oc[n][1] *= al0;
            oc[n][2] *= al1; oc[n][3] *= al1;
        }

        // --- O += P V (bf16x3) + row-sum via ones-column mma ---
        float ps[4] = {0.f, 0.f, 0.f, 0.f};
        #pragma unroll
        for (int ks = 0; ks < 4; ++ks) {
            uint32_t a0h, a1h, a2h, a3h, a0l, a1l, a2l, a3l;
            split2(sc[2*ks][0],   sc[2*ks][1],   a0h, a0l);
            split2(sc[2*ks][2],   sc[2*ks][3],   a1h, a1l);
            split2(sc[2*ks+1][0], sc[2*ks+1][1], a2h, a2l);
            split2(sc[2*ks+1][2], sc[2*ks+1][3], a3h, a3l);
            MMA16816(ps, a0h, a1h, a2h, a3h, ONESBF, ONESBF);
            MMA16816(ps, a0l, a1l, a2l, a3l, ONESBF, ONESBF);
            const uint32_t va = vbase + stoff + (uint32_t)ks * 2304;
            #pragma unroll
            for (int n = 0; n < 8; ++n) {
                uint32_t b0h, b1h, b0l, b1l;
                LDSM_X4_T(b0h, b1h, b0l, b1l, va + (uint32_t)n * 16);
                MMA16816(oc[n], a0h, a1h, a2h, a3h, b0h, b1h);
                MMA16816(oc[n], a0h, a1h, a2h, a3h, b0l, b1l);
                MMA16816(oc[n], a0l, a1l, a2l, a3l, b0h, b1h);
            }
        }
        l0r = l0r * al0 + ps[0];    // ones-column sum, replicated per lane
        l1r = l1r * al1 + ps[2];
    }

    // --- epilogue: normalize + tf32-round + store ---
    float invA = 1.f / l0r;
    float invB = 1.f / l1r;
    float* Ob = Outp + bofs + (size_t)row0 * Dn;
    #pragma unroll
    for (int n = 0; n < 8; ++n) {
        int cc = n * 8 + 2 * tig;
        *(float2*)&Ob[cc] =
            make_float2(tf32r(oc[n][0] * invA), tf32r(oc[n][1] * invA));
        *(float2*)(Ob + 8 * (size_t)Dn + cc) =
            make_float2(tf32r(oc[n][2] * invB), tf32r(oc[n][3] * invB));
    }
}

// ---------------------------------------------------------------------------
extern "C" void kernel_launch(void* const* d_in, const int* in_sizes, int n_in,
                              void* d_out, int out_size)
{
    const float* x   = (const float*)d_in[0];
    const int*   eff = (const int*)d_in[1];
    const float* Wq  = (const float*)d_in[2];
    const float* bq  = (const float*)d_in[3];
    const float* Wk  = (const float*)d_in[4];
    const float* bk  = (const float*)d_in[5];
    const float* Wv  = (const float*)d_in[6];
    const float* bv  = (const float*)d_in[7];
    const float* Wo  = (const float*)d_in[8];
    const float* bo  = (const float*)d_in[9];
    float* out = (float*)d_out;

    float *att, *xr, *wqr, *wkr, *wvr, *wor;
    cudaGetSymbolAddress((void**)&att, g_att);
    cudaGetSymbolAddress((void**)&xr,  g_xr);
    cudaGetSymbolAddress((void**)&wqr, g_wqr);
    cudaGetSymbolAddress((void**)&wkr, g_wkr);
    cudaGetSymbolAddress((void**)&wvr, g_wvr);
    cudaGetSymbolAddress((void**)&wor, g_wor);

    cudaFuncSetAttribute(gemm_mma<0>,
                         cudaFuncAttributeMaxDynamicSharedMemorySize, GSMEM);
    cudaFuncSetAttribute(gemm_mma<1>,
                         cudaFuncAttributeMaxDynamicSharedMemorySize, GSMEM);
    cudaFuncSetAttribute(attn6,
                         cudaFuncAttributeMaxDynamicSharedMemorySize, ATT_SMEM);

    prep_kernel<<<(Mn * Dn + 4 * Dn * Dn) / 1024, 256>>>(x, Wq, Wk, Wv, Wo);

    // fused QKV projection (24 n-tiles x 32 m-tiles)
    gemm_mma<1><<<dim3(24, 32), 256, GSMEM>>>(xr, wqr, wkr, wvr,
                                              bq, bk, bv, nullptr);

    attn6<<<dim3(Sn / 128, Hn, Bn), 256, ATT_SMEM>>>(eff, att);

    // O projection
    gemm_mma<0><<<dim3(8, 32), 256, GSMEM>>>(att, wor, nullptr, nullptr,
                                             bo, nullptr, nullptr, out);
}